// round 6
// baseline (speedup 1.0000x reference)
#include <cuda_runtime.h>
#include <cstdint>

#define NSEQ 1024
#define NRES 768
#define CM   64

// per-column weighted_avg scratch: wa[r][64]
__device__ float g_wa[NRES * CM];

__device__ __forceinline__ void fma4(float4& a, float s, const float4 w) {
    a.x += s * w.x; a.y += s * w.y; a.z += s * w.z; a.w += s * w.w;
}
__device__ __forceinline__ void xadd4(float4& a, int m) {
    a.x += __shfl_xor_sync(0xffffffffu, a.x, m);
    a.y += __shfl_xor_sync(0xffffffffu, a.y, m);
    a.z += __shfl_xor_sync(0xffffffffu, a.z, m);
    a.w += __shfl_xor_sync(0xffffffffu, a.w, m);
}
__device__ __forceinline__ uint32_t f2tf32(float f) {
    uint32_t r;
    asm("cvt.rna.tf32.f32 %0, %1;" : "=r"(r) : "f"(f));
    return r;
}
__device__ __forceinline__ void mma_tf32(float4& d,
    uint32_t a0, uint32_t a1, uint32_t a2, uint32_t a3,
    uint32_t b0, uint32_t b1) {
    asm volatile("mma.sync.aligned.m16n8k8.row.col.f32.tf32.tf32.f32 "
        "{%0,%1,%2,%3}, {%4,%5,%6,%7}, {%8,%9}, {%0,%1,%2,%3};"
        : "+f"(d.x), "+f"(d.y), "+f"(d.z), "+f"(d.w)
        : "r"(a0), "r"(a1), "r"(a2), "r"(a3), "r"(b0), "r"(b1));
}
__device__ __forceinline__ float sigf(float x) {
    return __fdividef(1.f, 1.f + __expf(-x));
}

// ---------------------------------------------------------------------------
// Kernel 1: per-column attention. grid = 768, 256 threads, occupancy 2.
// Main loop: warp processes 2 rows per round with coalesced LDG + width-16
// shuffle reductions (LN, K/V projection). No smem staging.
// ---------------------------------------------------------------------------
__global__ void __launch_bounds__(256, 2) msa_k1(
    const float* __restrict__ act,      // [S, R, C]
    const float* __restrict__ mask,     // [S, R]
    const float* __restrict__ ln_scale, // [64]
    const float* __restrict__ ln_bias,  // [64]
    const float* __restrict__ query_w,  // [64, 64]
    const float* __restrict__ key_w,    // [64, 8]
    const float* __restrict__ value_w)  // [64, 8]
{
    extern __shared__ float sm[];
    float* ks   = sm;              // 8192  : k[s][8]
    float* vs   = ks + 8192;       // 8192  : v[s][8]
    float* lsm  = vs + 8192;       // 8192  : logits / exp [s][8]
    float* msk  = lsm + 8192;      // 1024
    float* kws  = msk + 1024;      // 512
    float* vws  = kws + 512;       // 512
    float* scl  = vws + 512;       // 64
    float* bia  = scl + 64;        // 64
    float* qsum = bia + 64;        // 64
    float* qf   = qsum + 64;       // 64
    float* red  = qf + 64;         // 64   (8 warps x 8 heads)
    float* gmax = red + 64;        // 8
    float* invZ = gmax + 8;        // 8
    float* part = invZ + 8;        // 256
    float* Msum = part + 256;      // 1

    const int tid  = threadIdx.x;
    const int r    = blockIdx.x;
    const int lane = tid & 31;
    const int w    = tid >> 5;
    const int c4   = lane & 15;    // channel quad (4 ch)
    const int rsel = lane >> 4;    // which of 2 rows

    for (int i = tid; i < 512; i += 256) { kws[i] = key_w[i]; vws[i] = value_w[i]; }
    if (tid < 64) { scl[tid] = ln_scale[tid]; bia[tid] = ln_bias[tid]; qsum[tid] = 0.f; }
    if (tid == 64) *Msum = 0.f;
    __syncthreads();

    const float4* kw4 = (const float4*)kws;
    const float4* vw4 = (const float4*)vws;
    const float4 sc4 = ((const float4*)scl)[c4];
    const float4 bi4 = ((const float4*)bia)[c4];

    float lqs[4] = {0.f, 0.f, 0.f, 0.f};
    float lms = 0.f;

#pragma unroll 2
    for (int rnd = 0; rnd < 64; ++rnd) {
        const int row = (rnd << 4) + (w << 1) + rsel;
        const float4 t = *(const float4*)(act + ((size_t)row * NRES + r) * CM + c4 * 4);
        const float m = __ldg(mask + (size_t)row * NRES + r);

        float sum = t.x + t.y + t.z + t.w;
        sum += __shfl_xor_sync(0xffffffffu, sum, 1);
        sum += __shfl_xor_sync(0xffffffffu, sum, 2);
        sum += __shfl_xor_sync(0xffffffffu, sum, 4);
        sum += __shfl_xor_sync(0xffffffffu, sum, 8);
        const float mu = sum * (1.f / 64.f);
        float vv = (t.x-mu)*(t.x-mu) + (t.y-mu)*(t.y-mu)
                 + (t.z-mu)*(t.z-mu) + (t.w-mu)*(t.w-mu);
        vv += __shfl_xor_sync(0xffffffffu, vv, 1);
        vv += __shfl_xor_sync(0xffffffffu, vv, 2);
        vv += __shfl_xor_sync(0xffffffffu, vv, 4);
        vv += __shfl_xor_sync(0xffffffffu, vv, 8);
        const float rstd = rsqrtf(vv * (1.f / 64.f) + 1e-5f);

        float xn[4];
        xn[0] = (t.x - mu) * rstd * sc4.x + bi4.x;
        xn[1] = (t.y - mu) * rstd * sc4.y + bi4.y;
        xn[2] = (t.z - mu) * rstd * sc4.z + bi4.z;
        xn[3] = (t.w - mu) * rstd * sc4.w + bi4.w;
#pragma unroll
        for (int i = 0; i < 4; i++) lqs[i] += m * xn[i];

        float4 k0 = {0,0,0,0}, k1 = {0,0,0,0}, v0 = {0,0,0,0}, v1 = {0,0,0,0};
#pragma unroll
        for (int c = 0; c < 4; c++) {
            const int cg = c4 * 4 + c;
            fma4(k0, xn[c], kw4[cg*2]);   fma4(k1, xn[c], kw4[cg*2+1]);
            fma4(v0, xn[c], vw4[cg*2]);   fma4(v1, xn[c], vw4[cg*2+1]);
        }
        xadd4(k0, 1); xadd4(k0, 2); xadd4(k0, 4); xadd4(k0, 8);
        xadd4(k1, 1); xadd4(k1, 2); xadd4(k1, 4); xadd4(k1, 8);
        xadd4(v0, 1); xadd4(v0, 2); xadd4(v0, 4); xadd4(v0, 8);
        xadd4(v1, 1); xadd4(v1, 2); xadd4(v1, 4); xadd4(v1, 8);

        if (c4 == 0) { msk[row] = m; lms += m; }
        if (c4 < 4) {
            const float4 val = (c4 == 0) ? k0 : (c4 == 1) ? k1 : (c4 == 2) ? v0 : v1;
            float* dst = ((c4 < 2) ? ks : vs) + row * 8 + (c4 & 1) * 4;
            *(float4*)dst = val;
        }
    }

    // ---- qsum / Msum reductions ----
#pragma unroll
    for (int i = 0; i < 4; i++) lqs[i] += __shfl_xor_sync(0xffffffffu, lqs[i], 16);
    if (rsel == 0) {
#pragma unroll
        for (int i = 0; i < 4; i++) atomicAdd(&qsum[c4 * 4 + i], lqs[i]);
    }
    lms += __shfl_xor_sync(0xffffffffu, lms, 16);
    if (lane == 0) atomicAdd(Msum, lms);
    __syncthreads();

    // ---- q projection ----
    if (tid < 64) {
        const float invM = 1.f / (*Msum + 1e-10f);
        float acc = 0.f;
        for (int c = 0; c < 64; c++) acc += qsum[c] * query_w[c * 64 + tid];
        qf[tid] = acc * invM * 0.35355339059327373f;
    }
    __syncthreads();

    // ---- logits + max ----
    float lmax[8];
#pragma unroll
    for (int h = 0; h < 8; h++) lmax[h] = -3.4e38f;
#pragma unroll
    for (int it = 0; it < 4; it++) {
        const int s = tid + it * 256;
        const float4* kp = (const float4*)(ks + s * 8);
        const float4 k0 = kp[0], k1 = kp[1];
        const float b = 1e9f * (msk[s] - 1.f);
#pragma unroll
        for (int h = 0; h < 8; h++) {
            const float* q = qf + h * 8;
            float l = b + q[0]*k0.x + q[1]*k0.y + q[2]*k0.z + q[3]*k0.w
                        + q[4]*k1.x + q[5]*k1.y + q[6]*k1.z + q[7]*k1.w;
            lsm[s * 8 + h] = l;
            lmax[h] = fmaxf(lmax[h], l);
        }
    }
#pragma unroll
    for (int h = 0; h < 8; h++) {
#pragma unroll
        for (int off = 16; off; off >>= 1)
            lmax[h] = fmaxf(lmax[h], __shfl_xor_sync(0xffffffffu, lmax[h], off));
    }
    if (lane == 0) {
#pragma unroll
        for (int h = 0; h < 8; h++) red[w * 8 + h] = lmax[h];
    }
    __syncthreads();
    if (tid < 8) {
        float mm = red[tid];
#pragma unroll
        for (int ww = 1; ww < 8; ww++) mm = fmaxf(mm, red[ww * 8 + tid]);
        gmax[tid] = mm;
    }
    __syncthreads();

    // ---- exp + Z ----
    float zl[8];
#pragma unroll
    for (int h = 0; h < 8; h++) zl[h] = 0.f;
#pragma unroll
    for (int it = 0; it < 4; it++) {
        const int s = tid + it * 256;
#pragma unroll
        for (int h = 0; h < 8; h++) {
            const float e = __expf(lsm[s * 8 + h] - gmax[h]);
            lsm[s * 8 + h] = e;
            zl[h] += e;
        }
    }
#pragma unroll
    for (int h = 0; h < 8; h++) {
#pragma unroll
        for (int off = 16; off; off >>= 1)
            zl[h] += __shfl_xor_sync(0xffffffffu, zl[h], off);
    }
    if (lane == 0) {
#pragma unroll
        for (int h = 0; h < 8; h++) red[w * 8 + h] = zl[h];
    }
    __syncthreads();
    if (tid < 8) {
        float z = 0.f;
#pragma unroll
        for (int ww = 0; ww < 8; ww++) z += red[ww * 8 + tid];
        invZ[tid] = 1.f / z;
    }
    __syncthreads();

    // ---- weighted_avg ----
    {
        const int hd = tid & 63, q4 = tid >> 6;
        const int h = hd >> 3, d = hd & 7;
        float p = 0.f;
        const int s0 = q4 * 256;
        for (int s = s0; s < s0 + 256; ++s)
            p += lsm[s * 8 + h] * vs[s * 8 + d];
        part[tid] = p;
    }
    __syncthreads();
    if (tid < 64) {
        const int h = tid >> 3;
        g_wa[r * 64 + tid] =
            (part[tid] + part[tid + 64] + part[tid + 128] + part[tid + 192]) * invZ[h];
    }
}

// ---------------------------------------------------------------------------
// Kernel 2: gate + output via tf32 MMA. Row-major XN/G strips (stride 68),
// conflict-free scalar A-fragment loads, M=32 per warp, B fragment-packed.
// grid = (768, 4 tiles of 256 rows), 256 threads.
// ---------------------------------------------------------------------------
#define XS 68

__global__ void __launch_bounds__(256, 2) msa_k2(
    const float* __restrict__ act,
    const float* __restrict__ ln_scale, const float* __restrict__ ln_bias,
    const float* __restrict__ gating_w,  // [64, 64]  (c, j)
    const float* __restrict__ gating_b,  // [64]
    const float* __restrict__ output_w,  // [64, 64]  (j, o)
    const float* __restrict__ output_b,  // [64]
    float* __restrict__ out)             // [S, R, C]
{
    extern __shared__ float sm2[];
    float* xnf = sm2;              // 256 rows * 68 = 17408 (XN -> G -> OUT)
    float* gwf = xnf + 17408;      // 4096 : B-frag [n][k][lane] float2
    float* owf = gwf + 4096;       // 4096
    float* was = owf + 4096;       // 64
    float* gbs = was + 64;         // 64
    float* obs = gbs + 64;         // 64
    float* scl = obs + 64;         // 64
    float* bia = scl + 64;         // 64

    const int tid  = threadIdx.x;
    const int r    = blockIdx.x;
    const int s0   = blockIdx.y * 256;
    const int w    = tid >> 5, lane = tid & 31;
    const int c4   = lane & 15, rsel = lane >> 4;
    const int g    = lane >> 2, t = lane & 3;

    // ---- stage weights into B-fragment layout ----
    for (int i = tid; i < 4096; i += 256) {
        const int c = i >> 6, j = i & 63;
        const int kk = c >> 3, tt = c & 7;
        const int nn = j >> 3, gg = j & 7;
        const int off = ((nn * 8 + kk) * 32 + gg * 4 + (tt & 3)) * 2 + (tt >> 2);
        gwf[off] = __uint_as_float(f2tf32(gating_w[i]));
        owf[off] = __uint_as_float(f2tf32(output_w[i]));
    }
    if (tid < 64) {
        was[tid] = g_wa[r * 64 + tid];
        gbs[tid] = gating_b[tid];  obs[tid] = output_b[tid];
        scl[tid] = ln_scale[tid];  bia[tid] = ln_bias[tid];
    }
    __syncthreads();

    // ---- LN: warp owns rows w*32..w*32+31, coalesced row-major store ----
    {
        const float4 sc = ((const float4*)scl)[c4];
        const float4 bi = ((const float4*)bia)[c4];
#pragma unroll
        for (int rnd = 0; rnd < 16; rnd++) {
            const int row = w * 32 + rnd * 2 + rsel;
            const float4 tt = *(const float4*)(act + ((size_t)(s0 + row) * NRES + r) * CM + c4 * 4);
            float sum = tt.x + tt.y + tt.z + tt.w;
            sum += __shfl_xor_sync(0xffffffffu, sum, 1);
            sum += __shfl_xor_sync(0xffffffffu, sum, 2);
            sum += __shfl_xor_sync(0xffffffffu, sum, 4);
            sum += __shfl_xor_sync(0xffffffffu, sum, 8);
            const float mu = sum * (1.f / 64.f);
            float vv = (tt.x-mu)*(tt.x-mu) + (tt.y-mu)*(tt.y-mu)
                     + (tt.z-mu)*(tt.z-mu) + (tt.w-mu)*(tt.w-mu);
            vv += __shfl_xor_sync(0xffffffffu, vv, 1);
            vv += __shfl_xor_sync(0xffffffffu, vv, 2);
            vv += __shfl_xor_sync(0xffffffffu, vv, 4);
            vv += __shfl_xor_sync(0xffffffffu, vv, 8);
            const float rstd = rsqrtf(vv * (1.f / 64.f) + 1e-5f);
            float4 o;
            o.x = __uint_as_float(f2tf32((tt.x - mu) * rstd * sc.x + bi.x));
            o.y = __uint_as_float(f2tf32((tt.y - mu) * rstd * sc.y + bi.y));
            o.z = __uint_as_float(f2tf32((tt.z - mu) * rstd * sc.z + bi.z));
            o.w = __uint_as_float(f2tf32((tt.w - mu) * rstd * sc.w + bi.w));
            *(float4*)(xnf + row * XS + c4 * 4) = o;
        }
    }
    __syncwarp();   // strips are warp-private

    const int rb = w * 32;
    float* st0 = xnf + rb * XS;          // rows rb..rb+15
    float* st1 = xnf + (rb + 16) * XS;   // rows rb+16..rb+31

    // ---- GEMM1: logits = XN @ GW ----
    float4 acc0[8], acc1[8];
#pragma unroll
    for (int n = 0; n < 8; n++) { acc0[n] = make_float4(0,0,0,0); acc1[n] = make_float4(0,0,0,0); }
#pragma unroll
    for (int k = 0; k < 8; k++) {
        const int kc = k * 8 + t;
        const uint32_t a00 = __float_as_uint(st0[g * XS + kc]);
        const uint32_t a01 = __float_as_uint(st0[(g + 8) * XS + kc]);
        const uint32_t a02 = __float_as_uint(st0[g * XS + kc + 4]);
        const uint32_t a03 = __float_as_uint(st0[(g + 8) * XS + kc + 4]);
        const uint32_t a10 = __float_as_uint(st1[g * XS + kc]);
        const uint32_t a11 = __float_as_uint(st1[(g + 8) * XS + kc]);
        const uint32_t a12 = __float_as_uint(st1[g * XS + kc + 4]);
        const uint32_t a13 = __float_as_uint(st1[(g + 8) * XS + kc + 4]);
#pragma unroll
        for (int n = 0; n < 8; n++) {
            const float2 b = *(const float2*)(gwf + ((n * 8 + k) * 32 + lane) * 2);
            mma_tf32(acc0[n], a00, a01, a02, a03,
                     __float_as_uint(b.x), __float_as_uint(b.y));
            mma_tf32(acc1[n], a10, a11, a12, a13,
                     __float_as_uint(b.x), __float_as_uint(b.y));
        }
    }
    __syncwarp();

    // ---- gate: G = wa*sigmoid(logit+gb), row-major float2 stores ----
#pragma unroll
    for (int n = 0; n < 8; n++) {
        const int c0 = n * 8 + 2 * t;
        const float w0 = was[c0], w1 = was[c0 + 1];
        const float b0 = gbs[c0], b1 = gbs[c0 + 1];
        float2 p;
        p.x = __uint_as_float(f2tf32(w0 * sigf(acc0[n].x + b0)));
        p.y = __uint_as_float(f2tf32(w1 * sigf(acc0[n].y + b1)));
        *(float2*)(st0 + g * XS + c0) = p;
        p.x = __uint_as_float(f2tf32(w0 * sigf(acc0[n].z + b0)));
        p.y = __uint_as_float(f2tf32(w1 * sigf(acc0[n].w + b1)));
        *(float2*)(st0 + (g + 8) * XS + c0) = p;
        p.x = __uint_as_float(f2tf32(w0 * sigf(acc1[n].x + b0)));
        p.y = __uint_as_float(f2tf32(w1 * sigf(acc1[n].y + b1)));
        *(float2*)(st1 + g * XS + c0) = p;
        p.x = __uint_as_float(f2tf32(w0 * sigf(acc1[n].z + b0)));
        p.y = __uint_as_float(f2tf32(w1 * sigf(acc1[n].w + b1)));
        *(float2*)(st1 + (g + 8) * XS + c0) = p;
    }
    __syncwarp();

    // ---- GEMM2: OUT = G @ OW + ob ----
    float4 o0[8], o1[8];
#pragma unroll
    for (int n = 0; n < 8; n++) {
        const int c0 = n * 8 + 2 * t;
        o0[n] = make_float4(obs[c0], obs[c0+1], obs[c0], obs[c0+1]);
        o1[n] = o0[n];
    }
#pragma unroll
    for (int k = 0; k < 8; k++) {
        const int kc = k * 8 + t;
        const uint32_t a00 = __float_as_uint(st0[g * XS + kc]);
        const uint32_t a01 = __float_as_uint(st0[(g + 8) * XS + kc]);
        const uint32_t a02 = __float_as_uint(st0[g * XS + kc + 4]);
        const uint32_t a03 = __float_as_uint(st0[(g + 8) * XS + kc + 4]);
        const uint32_t a10 = __float_as_uint(st1[g * XS + kc]);
        const uint32_t a11 = __float_as_uint(st1[(g + 8) * XS + kc]);
        const uint32_t a12 = __float_as_uint(st1[g * XS + kc + 4]);
        const uint32_t a13 = __float_as_uint(st1[(g + 8) * XS + kc + 4]);
#pragma unroll
        for (int n = 0; n < 8; n++) {
            const float2 b = *(const float2*)(owf + ((n * 8 + k) * 32 + lane) * 2);
            mma_tf32(o0[n], a00, a01, a02, a03,
                     __float_as_uint(b.x), __float_as_uint(b.y));
            mma_tf32(o1[n], a10, a11, a12, a13,
                     __float_as_uint(b.x), __float_as_uint(b.y));
        }
    }
    __syncwarp();

    // ---- stage outputs row-major (G no longer needed) ----
#pragma unroll
    for (int n = 0; n < 8; n++) {
        const int c0 = n * 8 + 2 * t;
        *(float2*)(st0 + g * XS + c0)       = make_float2(o0[n].x, o0[n].y);
        *(float2*)(st0 + (g + 8) * XS + c0) = make_float2(o0[n].z, o0[n].w);
        *(float2*)(st1 + g * XS + c0)       = make_float2(o1[n].x, o1[n].y);
        *(float2*)(st1 + (g + 8) * XS + c0) = make_float2(o1[n].z, o1[n].w);
    }
    __syncwarp();

    // ---- coalesced STG ----
#pragma unroll
    for (int rnd = 0; rnd < 16; rnd++) {
        const int row = w * 32 + rnd * 2 + rsel;
        const float4 v = *(const float4*)(xnf + row * XS + c4 * 4);
        *(float4*)(out + ((size_t)(s0 + row) * NRES + r) * CM + c4 * 4) = v;
    }
}

// ---------------------------------------------------------------------------
#define K1_SMEM (27232 * 4)
#define K2_SMEM (25920 * 4)

extern "C" void kernel_launch(void* const* d_in, const int* in_sizes, int n_in,
                              void* d_out, int out_size) {
    (void)in_sizes; (void)n_in; (void)out_size;
    const float* act      = (const float*)d_in[0];
    const float* mask     = (const float*)d_in[1];
    const float* ln_scale = (const float*)d_in[2];
    const float* ln_bias  = (const float*)d_in[3];
    const float* query_w  = (const float*)d_in[4];
    const float* key_w    = (const float*)d_in[5];
    const float* value_w  = (const float*)d_in[6];
    const float* gating_w = (const float*)d_in[7];
    const float* gating_b = (const float*)d_in[8];
    const float* output_w = (const float*)d_in[9];
    const float* output_b = (const float*)d_in[10];
    float* out = (float*)d_out;

    cudaFuncSetAttribute(msa_k1, cudaFuncAttributeMaxDynamicSharedMemorySize, K1_SMEM);
    cudaFuncSetAttribute(msa_k2, cudaFuncAttributeMaxDynamicSharedMemorySize, K2_SMEM);

    msa_k1<<<NRES, 256, K1_SMEM>>>(act, mask, ln_scale, ln_bias, query_w, key_w, value_w);
    msa_k2<<<dim3(NRES, 4), 256, K2_SMEM>>>(act, ln_scale, ln_bias,
                                            gating_w, gating_b, output_w, output_b, out);
}

// round 8
// speedup vs baseline: 1.2654x; 1.2654x over previous
#include <cuda_runtime.h>
#include <cstdint>

#define NSEQ 1024
#define NRES 768
#define CM   64

// scratch
__device__ float g_wa[NRES * CM];                // weighted_avg per column
__device__ float g_kv[(size_t)NRES * NSEQ * 16]; // [r][s][0..7]=k, [8..15]=v
__device__ float g_mskd[NRES * NSEQ];            // mask transposed [r][s]
__device__ float g_qsp[NRES * 4 * 64];           // partial masked sums
__device__ float g_msp[NRES * 4];                // partial mask sums

__device__ __forceinline__ void fma4(float4& a, float s, const float4 w) {
    a.x += s * w.x; a.y += s * w.y; a.z += s * w.z; a.w += s * w.w;
}
__device__ __forceinline__ void xadd4(float4& a, int m) {
    a.x += __shfl_xor_sync(0xffffffffu, a.x, m);
    a.y += __shfl_xor_sync(0xffffffffu, a.y, m);
    a.z += __shfl_xor_sync(0xffffffffu, a.z, m);
    a.w += __shfl_xor_sync(0xffffffffu, a.w, m);
}
__device__ __forceinline__ uint32_t f2tf32(float f) {
    uint32_t r;
    asm("cvt.rna.tf32.f32 %0, %1;" : "=r"(r) : "f"(f));
    return r;
}
__device__ __forceinline__ void mma_tf32(float4& d,
    uint32_t a0, uint32_t a1, uint32_t a2, uint32_t a3,
    uint32_t b0, uint32_t b1) {
    asm volatile("mma.sync.aligned.m16n8k8.row.col.f32.tf32.tf32.f32 "
        "{%0,%1,%2,%3}, {%4,%5,%6,%7}, {%8,%9}, {%0,%1,%2,%3};"
        : "+f"(d.x), "+f"(d.y), "+f"(d.z), "+f"(d.w)
        : "r"(a0), "r"(a1), "r"(a2), "r"(a3), "r"(b0), "r"(b1));
}
__device__ __forceinline__ float sigf(float x) {
    return __fdividef(1.f, 1.f + __expf(-x));
}

// ---------------------------------------------------------------------------
// Kernel 1a: LN + K/V projection for a 256-row tile of one column.
// grid = (768, 4), 256 threads, quad-lane-per-row (16 ch/lane).
// ---------------------------------------------------------------------------
__global__ void __launch_bounds__(256, 3) msa_k1a(
    const float* __restrict__ act,      // [S, R, C]
    const float* __restrict__ mask,     // [S, R]
    const float* __restrict__ ln_scale, const float* __restrict__ ln_bias,
    const float* __restrict__ key_w,    // [64, 8]
    const float* __restrict__ value_w)  // [64, 8]
{
    __shared__ float kws[512], vws[512], scl[64], bia[64], qs[64];
    __shared__ float mssum;

    const int tid  = threadIdx.x;
    const int r    = blockIdx.x;
    const int tile = blockIdx.y;
    const int lane = tid & 31;
    const int Q    = lane & 3;       // channel quarter (16 ch)
    const int row4 = tid >> 2;       // row 0..63 within pass

    for (int i = tid; i < 512; i += 256) { kws[i] = key_w[i]; vws[i] = value_w[i]; }
    if (tid < 64) { scl[tid] = ln_scale[tid]; bia[tid] = ln_bias[tid]; qs[tid] = 0.f; }
    if (tid == 0) mssum = 0.f;
    __syncthreads();

    const float4* kw4 = (const float4*)kws;
    const float4* vw4 = (const float4*)vws;

    float lqs[16];
#pragma unroll
    for (int i = 0; i < 16; i++) lqs[i] = 0.f;
    float lms = 0.f;

#pragma unroll
    for (int pass = 0; pass < 4; ++pass) {
        const int s = tile * 256 + pass * 64 + row4;
        const float4* xp = (const float4*)(act + ((size_t)s * NRES + r) * CM + Q * 16);
        float x[16];
#pragma unroll
        for (int i = 0; i < 4; i++) {
            const float4 t = xp[i];
            x[i*4+0] = t.x; x[i*4+1] = t.y; x[i*4+2] = t.z; x[i*4+3] = t.w;
        }
        float m = 0.f;
        if (Q == 0) m = mask[(size_t)s * NRES + r];
        m = __shfl_sync(0xffffffffu, m, lane & ~3);
        if (Q == 0) { lms += m; g_mskd[r * NSEQ + s] = m; }

        float sum = 0.f;
#pragma unroll
        for (int i = 0; i < 16; i++) sum += x[i];
        sum += __shfl_xor_sync(0xffffffffu, sum, 1);
        sum += __shfl_xor_sync(0xffffffffu, sum, 2);
        const float mu = sum * (1.f / 64.f);
        float vv = 0.f;
#pragma unroll
        for (int i = 0; i < 16; i++) { float d = x[i] - mu; vv += d * d; }
        vv += __shfl_xor_sync(0xffffffffu, vv, 1);
        vv += __shfl_xor_sync(0xffffffffu, vv, 2);
        const float rstd = rsqrtf(vv * (1.f / 64.f) + 1e-5f);

        float4 k0 = {0,0,0,0}, k1 = {0,0,0,0}, v0 = {0,0,0,0}, v1 = {0,0,0,0};
#pragma unroll
        for (int c = 0; c < 16; c++) {
            const int cg = Q * 16 + c;
            const float xn = (x[c] - mu) * rstd * scl[cg] + bia[cg];
            lqs[c] += m * xn;
            fma4(k0, xn, kw4[cg*2]);   fma4(k1, xn, kw4[cg*2+1]);
            fma4(v0, xn, vw4[cg*2]);   fma4(v1, xn, vw4[cg*2+1]);
        }
        xadd4(k0, 1); xadd4(k0, 2);
        xadd4(k1, 1); xadd4(k1, 2);
        xadd4(v0, 1); xadd4(v0, 2);
        xadd4(v1, 1); xadd4(v1, 2);

        const float4 val = (Q == 0) ? k0 : (Q == 1) ? k1 : (Q == 2) ? v0 : v1;
        ((float4*)(g_kv + ((size_t)r * NSEQ + s) * 16))[Q] = val;   // coalesced
    }

    // reduce lqs across rows (lanes with same Q)
#pragma unroll
    for (int i = 0; i < 16; i++) {
        float v = lqs[i];
        v += __shfl_xor_sync(0xffffffffu, v, 4);
        v += __shfl_xor_sync(0xffffffffu, v, 8);
        v += __shfl_xor_sync(0xffffffffu, v, 16);
        lqs[i] = v;
    }
    if (lane < 4) {
#pragma unroll
        for (int i = 0; i < 16; i++) atomicAdd(&qs[lane * 16 + i], lqs[i]);
    }
    lms += __shfl_xor_sync(0xffffffffu, lms, 4);
    lms += __shfl_xor_sync(0xffffffffu, lms, 8);
    lms += __shfl_xor_sync(0xffffffffu, lms, 16);
    if (lane == 0) atomicAdd(&mssum, lms);
    __syncthreads();

    if (tid < 64) g_qsp[(r * 4 + tile) * 64 + tid] = qs[tid];
    if (tid == 0) g_msp[r * 4 + tile] = mssum;
}

// ---------------------------------------------------------------------------
// Kernel 1b: softmax attention for one column. grid = 768, 256 threads.
// ---------------------------------------------------------------------------
__global__ void __launch_bounds__(256, 2) msa_k1b(
    const float* __restrict__ query_w)  // [64, 64]
{
    extern __shared__ float sm[];
    float* ks   = sm;              // 8192
    float* vs   = ks + 8192;       // 8192
    float* lsm  = vs + 8192;       // 8192
    float* msk  = lsm + 8192;      // 1024
    float* qsum = msk + 1024;      // 64
    float* qf   = qsum + 64;       // 64
    float* red  = qf + 64;         // 64
    float* gmax = red + 64;        // 8
    float* invZ = gmax + 8;        // 8
    float* part = invZ + 8;        // 256
    float* Msum = part + 256;      // 1     -> total 26065 floats

    const int tid  = threadIdx.x;
    const int r    = blockIdx.x;
    const int lane = tid & 31;
    const int w    = tid >> 5;

    // bulk-coalesced k/v load
    const float4* kv4 = (const float4*)(g_kv + (size_t)r * NSEQ * 16);
    float4* ks4 = (float4*)ks;
    float4* vs4 = (float4*)vs;
    for (int i = tid; i < 4096; i += 256) {
        const int s = i >> 2, q = i & 3;
        const float4 v = kv4[i];
        if (q < 2) ks4[s * 2 + q] = v;
        else       vs4[s * 2 + (q - 2)] = v;
    }
    for (int i = tid; i < 1024; i += 256) msk[i] = g_mskd[r * NSEQ + i];
    if (tid < 64) {
        float a = 0.f;
#pragma unroll
        for (int t = 0; t < 4; t++) a += g_qsp[(r * 4 + t) * 64 + tid];
        qsum[tid] = a;
    }
    if (tid == 64) {
        float a = 0.f;
#pragma unroll
        for (int t = 0; t < 4; t++) a += g_msp[r * 4 + t];
        *Msum = a;
    }
    __syncthreads();

    // q projection
    if (tid < 64) {
        const float invM = 1.f / (*Msum + 1e-10f);
        float acc = 0.f;
        for (int c = 0; c < 64; c++) acc += qsum[c] * query_w[c * 64 + tid];
        qf[tid] = acc * invM * 0.35355339059327373f;
    }
    __syncthreads();

    // logits + max
    float lmax[8];
#pragma unroll
    for (int h = 0; h < 8; h++) lmax[h] = -3.4e38f;
#pragma unroll
    for (int it = 0; it < 4; it++) {
        const int s = tid + it * 256;
        const float4* kp = (const float4*)(ks + s * 8);
        const float4 k0 = kp[0], k1 = kp[1];
        const float b = 1e9f * (msk[s] - 1.f);
#pragma unroll
        for (int h = 0; h < 8; h++) {
            const float* q = qf + h * 8;
            float l = b + q[0]*k0.x + q[1]*k0.y + q[2]*k0.z + q[3]*k0.w
                        + q[4]*k1.x + q[5]*k1.y + q[6]*k1.z + q[7]*k1.w;
            lsm[s * 8 + h] = l;
            lmax[h] = fmaxf(lmax[h], l);
        }
    }
#pragma unroll
    for (int h = 0; h < 8; h++) {
#pragma unroll
        for (int off = 16; off; off >>= 1)
            lmax[h] = fmaxf(lmax[h], __shfl_xor_sync(0xffffffffu, lmax[h], off));
    }
    if (lane == 0) {
#pragma unroll
        for (int h = 0; h < 8; h++) red[w * 8 + h] = lmax[h];
    }
    __syncthreads();
    if (tid < 8) {
        float mm = red[tid];
#pragma unroll
        for (int ww = 1; ww < 8; ww++) mm = fmaxf(mm, red[ww * 8 + tid]);
        gmax[tid] = mm;
    }
    __syncthreads();

    // exp + Z
    float zl[8];
#pragma unroll
    for (int h = 0; h < 8; h++) zl[h] = 0.f;
#pragma unroll
    for (int it = 0; it < 4; it++) {
        const int s = tid + it * 256;
#pragma unroll
        for (int h = 0; h < 8; h++) {
            const float e = __expf(lsm[s * 8 + h] - gmax[h]);
            lsm[s * 8 + h] = e;
            zl[h] += e;
        }
    }
#pragma unroll
    for (int h = 0; h < 8; h++) {
#pragma unroll
        for (int off = 16; off; off >>= 1)
            zl[h] += __shfl_xor_sync(0xffffffffu, zl[h], off);
    }
    if (lane == 0) {
#pragma unroll
        for (int h = 0; h < 8; h++) red[w * 8 + h] = zl[h];
    }
    __syncthreads();
    if (tid < 8) {
        float z = 0.f;
#pragma unroll
        for (int ww = 0; ww < 8; ww++) z += red[ww * 8 + tid];
        invZ[tid] = 1.f / z;
    }
    __syncthreads();

    // weighted_avg
    {
        const int hd = tid & 63, q4 = tid >> 6;
        const int h = hd >> 3, d = hd & 7;
        float p = 0.f;
        const int s0 = q4 * 256;
        for (int s = s0; s < s0 + 256; ++s)
            p += lsm[s * 8 + h] * vs[s * 8 + d];
        part[tid] = p;
    }
    __syncthreads();
    if (tid < 64) {
        const int h = tid >> 3;
        g_wa[r * 64 + tid] =
            (part[tid] + part[tid + 64] + part[tid + 128] + part[tid + 192]) * invZ[h];
    }
}

// ---------------------------------------------------------------------------
// Kernel 2: gate + output via tf32 MMA (Round-6 version, measured 196 us).
// ---------------------------------------------------------------------------
#define XS 68

__global__ void __launch_bounds__(256, 2) msa_k2(
    const float* __restrict__ act,
    const float* __restrict__ ln_scale, const float* __restrict__ ln_bias,
    const float* __restrict__ gating_w,  // [64, 64]
    const float* __restrict__ gating_b,  // [64]
    const float* __restrict__ output_w,  // [64, 64]
    const float* __restrict__ output_b,  // [64]
    float* __restrict__ out)             // [S, R, C]
{
    extern __shared__ float sm2[];
    float* xnf = sm2;              // 256 rows * 68 = 17408
    float* gwf = xnf + 17408;      // 4096
    float* owf = gwf + 4096;       // 4096
    float* was = owf + 4096;       // 64
    float* gbs = was + 64;         // 64
    float* obs = gbs + 64;         // 64
    float* scl = obs + 64;         // 64
    float* bia = scl + 64;         // 64

    const int tid  = threadIdx.x;
    const int r    = blockIdx.x;
    const int s0   = blockIdx.y * 256;
    const int w    = tid >> 5, lane = tid & 31;
    const int c4   = lane & 15, rsel = lane >> 4;
    const int g    = lane >> 2, t = lane & 3;

    for (int i = tid; i < 4096; i += 256) {
        const int c = i >> 6, j = i & 63;
        const int kk = c >> 3, tt = c & 7;
        const int nn = j >> 3, gg = j & 7;
        const int off = ((nn * 8 + kk) * 32 + gg * 4 + (tt & 3)) * 2 + (tt >> 2);
        gwf[off] = __uint_as_float(f2tf32(gating_w[i]));
        owf[off] = __uint_as_float(f2tf32(output_w[i]));
    }
    if (tid < 64) {
        was[tid] = g_wa[r * 64 + tid];
        gbs[tid] = gating_b[tid];  obs[tid] = output_b[tid];
        scl[tid] = ln_scale[tid];  bia[tid] = ln_bias[tid];
    }
    __syncthreads();

    {
        const float4 sc = ((const float4*)scl)[c4];
        const float4 bi = ((const float4*)bia)[c4];
#pragma unroll
        for (int rnd = 0; rnd < 16; rnd++) {
            const int row = w * 32 + rnd * 2 + rsel;
            const float4 tt = *(const float4*)(act + ((size_t)(s0 + row) * NRES + r) * CM + c4 * 4);
            float sum = tt.x + tt.y + tt.z + tt.w;
            sum += __shfl_xor_sync(0xffffffffu, sum, 1);
            sum += __shfl_xor_sync(0xffffffffu, sum, 2);
            sum += __shfl_xor_sync(0xffffffffu, sum, 4);
            sum += __shfl_xor_sync(0xffffffffu, sum, 8);
            const float mu = sum * (1.f / 64.f);
            float vv = (tt.x-mu)*(tt.x-mu) + (tt.y-mu)*(tt.y-mu)
                     + (tt.z-mu)*(tt.z-mu) + (tt.w-mu)*(tt.w-mu);
            vv += __shfl_xor_sync(0xffffffffu, vv, 1);
            vv += __shfl_xor_sync(0xffffffffu, vv, 2);
            vv += __shfl_xor_sync(0xffffffffu, vv, 4);
            vv += __shfl_xor_sync(0xffffffffu, vv, 8);
            const float rstd = rsqrtf(vv * (1.f / 64.f) + 1e-5f);
            float4 o;
            o.x = __uint_as_float(f2tf32((tt.x - mu) * rstd * sc.x + bi.x));
            o.y = __uint_as_float(f2tf32((tt.y - mu) * rstd * sc.y + bi.y));
            o.z = __uint_as_float(f2tf32((tt.z - mu) * rstd * sc.z + bi.z));
            o.w = __uint_as_float(f2tf32((tt.w - mu) * rstd * sc.w + bi.w));
            *(float4*)(xnf + row * XS + c4 * 4) = o;
        }
    }
    __syncwarp();

    const int rb = w * 32;
    float* st0 = xnf + rb * XS;
    float* st1 = xnf + (rb + 16) * XS;

    float4 acc0[8], acc1[8];
#pragma unroll
    for (int n = 0; n < 8; n++) { acc0[n] = make_float4(0,0,0,0); acc1[n] = make_float4(0,0,0,0); }
#pragma unroll
    for (int k = 0; k < 8; k++) {
        const int kc = k * 8 + t;
        const uint32_t a00 = __float_as_uint(st0[g * XS + kc]);
        const uint32_t a01 = __float_as_uint(st0[(g + 8) * XS + kc]);
        const uint32_t a02 = __float_as_uint(st0[g * XS + kc + 4]);
        const uint32_t a03 = __float_as_uint(st0[(g + 8) * XS + kc + 4]);
        const uint32_t a10 = __float_as_uint(st1[g * XS + kc]);
        const uint32_t a11 = __float_as_uint(st1[(g + 8) * XS + kc]);
        const uint32_t a12 = __float_as_uint(st1[g * XS + kc + 4]);
        const uint32_t a13 = __float_as_uint(st1[(g + 8) * XS + kc + 4]);
#pragma unroll
        for (int n = 0; n < 8; n++) {
            const float2 b = *(const float2*)(gwf + ((n * 8 + k) * 32 + lane) * 2);
            mma_tf32(acc0[n], a00, a01, a02, a03,
                     __float_as_uint(b.x), __float_as_uint(b.y));
            mma_tf32(acc1[n], a10, a11, a12, a13,
                     __float_as_uint(b.x), __float_as_uint(b.y));
        }
    }
    __syncwarp();

#pragma unroll
    for (int n = 0; n < 8; n++) {
        const int c0 = n * 8 + 2 * t;
        const float w0 = was[c0], w1 = was[c0 + 1];
        const float b0 = gbs[c0], b1 = gbs[c0 + 1];
        float2 p;
        p.x = __uint_as_float(f2tf32(w0 * sigf(acc0[n].x + b0)));
        p.y = __uint_as_float(f2tf32(w1 * sigf(acc0[n].y + b1)));
        *(float2*)(st0 + g * XS + c0) = p;
        p.x = __uint_as_float(f2tf32(w0 * sigf(acc0[n].z + b0)));
        p.y = __uint_as_float(f2tf32(w1 * sigf(acc0[n].w + b1)));
        *(float2*)(st0 + (g + 8) * XS + c0) = p;
        p.x = __uint_as_float(f2tf32(w0 * sigf(acc1[n].x + b0)));
        p.y = __uint_as_float(f2tf32(w1 * sigf(acc1[n].y + b1)));
        *(float2*)(st1 + g * XS + c0) = p;
        p.x = __uint_as_float(f2tf32(w0 * sigf(acc1[n].z + b0)));
        p.y = __uint_as_float(f2tf32(w1 * sigf(acc1[n].w + b1)));
        *(float2*)(st1 + (g + 8) * XS + c0) = p;
    }
    __syncwarp();

    float4 o0[8], o1[8];
#pragma unroll
    for (int n = 0; n < 8; n++) {
        const int c0 = n * 8 + 2 * t;
        o0[n] = make_float4(obs[c0], obs[c0+1], obs[c0], obs[c0+1]);
        o1[n] = o0[n];
    }
#pragma unroll
    for (int k = 0; k < 8; k++) {
        const int kc = k * 8 + t;
        const uint32_t a00 = __float_as_uint(st0[g * XS + kc]);
        const uint32_t a01 = __float_as_uint(st0[(g + 8) * XS + kc]);
        const uint32_t a02 = __float_as_uint(st0[g * XS + kc + 4]);
        const uint32_t a03 = __float_as_uint(st0[(g + 8) * XS + kc + 4]);
        const uint32_t a10 = __float_as_uint(st1[g * XS + kc]);
        const uint32_t a11 = __float_as_uint(st1[(g + 8) * XS + kc]);
        const uint32_t a12 = __float_as_uint(st1[g * XS + kc + 4]);
        const uint32_t a13 = __float_as_uint(st1[(g + 8) * XS + kc + 4]);
#pragma unroll
        for (int n = 0; n < 8; n++) {
            const float2 b = *(const float2*)(owf + ((n * 8 + k) * 32 + lane) * 2);
            mma_tf32(o0[n], a00, a01, a02, a03,
                     __float_as_uint(b.x), __float_as_uint(b.y));
            mma_tf32(o1[n], a10, a11, a12, a13,
                     __float_as_uint(b.x), __float_as_uint(b.y));
        }
    }
    __syncwarp();

#pragma unroll
    for (int n = 0; n < 8; n++) {
        const int c0 = n * 8 + 2 * t;
        *(float2*)(st0 + g * XS + c0)       = make_float2(o0[n].x, o0[n].y);
        *(float2*)(st0 + (g + 8) * XS + c0) = make_float2(o0[n].z, o0[n].w);
        *(float2*)(st1 + g * XS + c0)       = make_float2(o1[n].x, o1[n].y);
        *(float2*)(st1 + (g + 8) * XS + c0) = make_float2(o1[n].z, o1[n].w);
    }
    __syncwarp();

#pragma unroll
    for (int rnd = 0; rnd < 16; rnd++) {
        const int row = w * 32 + rnd * 2 + rsel;
        const float4 v = *(const float4*)(xnf + row * XS + c4 * 4);
        *(float4*)(out + ((size_t)(s0 + row) * NRES + r) * CM + c4 * 4) = v;
    }
}

// ---------------------------------------------------------------------------
#define K1B_SMEM (26065 * 4)
#define K2_SMEM  (25920 * 4)

extern "C" void kernel_launch(void* const* d_in, const int* in_sizes, int n_in,
                              void* d_out, int out_size) {
    (void)in_sizes; (void)n_in; (void)out_size;
    const float* act      = (const float*)d_in[0];
    const float* mask     = (const float*)d_in[1];
    const float* ln_scale = (const float*)d_in[2];
    const float* ln_bias  = (const float*)d_in[3];
    const float* query_w  = (const float*)d_in[4];
    const float* key_w    = (const float*)d_in[5];
    const float* value_w  = (const float*)d_in[6];
    const float* gating_w = (const float*)d_in[7];
    const float* gating_b = (const float*)d_in[8];
    const float* output_w = (const float*)d_in[9];
    const float* output_b = (const float*)d_in[10];
    float* out = (float*)d_out;

    cudaFuncSetAttribute(msa_k1b, cudaFuncAttributeMaxDynamicSharedMemorySize, K1B_SMEM);
    cudaFuncSetAttribute(msa_k2,  cudaFuncAttributeMaxDynamicSharedMemorySize, K2_SMEM);

    msa_k1a<<<dim3(NRES, 4), 256>>>(act, mask, ln_scale, ln_bias, key_w, value_w);
    msa_k1b<<<NRES, 256, K1B_SMEM>>>(query_w);
    msa_k2<<<dim3(NRES, 4), 256, K2_SMEM>>>(act, ln_scale, ln_bias,
                                            gating_w, gating_b, output_w, output_b, out);
}

// round 9
// speedup vs baseline: 3.1367x; 2.4788x over previous
#include <cuda_runtime.h>
#include <cstdint>

#define NSEQ 1024
#define NRES 768
#define CM   64

// scratch
__device__ float g_wa[NRES * CM];                // weighted_avg per column
__device__ float g_kv[(size_t)NRES * NSEQ * 16]; // [r][s][0..7]=k, [8..15]=v
__device__ float g_mskd[NRES * NSEQ];            // mask transposed [r][s]
__device__ float g_qsp[NRES * 8 * 64];           // partial masked sums per s-tile
__device__ float g_msp[NRES * 8];                // partial mask sums per s-tile

__device__ __forceinline__ void fma4(float4& a, float s, const float4 w) {
    a.x += s * w.x; a.y += s * w.y; a.z += s * w.z; a.w += s * w.w;
}
__device__ __forceinline__ uint32_t f2tf32(float f) {
    uint32_t r;
    asm("cvt.rna.tf32.f32 %0, %1;" : "=r"(r) : "f"(f));
    return r;
}
__device__ __forceinline__ void mma_tf32(float4& d,
    uint32_t a0, uint32_t a1, uint32_t a2, uint32_t a3,
    uint32_t b0, uint32_t b1) {
    asm volatile("mma.sync.aligned.m16n8k8.row.col.f32.tf32.tf32.f32 "
        "{%0,%1,%2,%3}, {%4,%5,%6,%7}, {%8,%9}, {%0,%1,%2,%3};"
        : "+f"(d.x), "+f"(d.y), "+f"(d.z), "+f"(d.w)
        : "r"(a0), "r"(a1), "r"(a2), "r"(a3), "r"(b0), "r"(b1));
}
__device__ __forceinline__ float sigf(float x) {
    return __fdividef(1.f, 1.f + __expf(-x));
}

// ---------------------------------------------------------------------------
// Kernel 1a: LN + K/V projection. Block = 8 columns x 128 rows, 4 chunks of
// 32 rows. grid = (96, 8), 256 threads. Coalesced 2KB-row LDG, zero-shuffle
// per-thread LN/KV, warp-per-column qsum pass.
// ---------------------------------------------------------------------------
#define RST 68   // smem stride per (s,c) row

__global__ void __launch_bounds__(256) msa_k1a(
    const float* __restrict__ act,      // [S, R, C]
    const float* __restrict__ mask,     // [S, R]
    const float* __restrict__ ln_scale, const float* __restrict__ ln_bias,
    const float* __restrict__ key_w,    // [64, 8]
    const float* __restrict__ value_w)  // [64, 8]
{
    extern __shared__ float smk[];
    float* xch = smk;            // 32*8*68 = 17408 : x -> xn in place
    float* mch = xch + 17408;    // 256 : mask [s][c]
    float* kws = mch + 256;      // 512
    float* vws = kws + 512;      // 512
    float* scl = vws + 512;      // 64
    float* bia = scl + 64;       // 64

    const int tid  = threadIdx.x;
    const int r0   = blockIdx.x * 8;
    const int ty   = blockIdx.y;
    const int s0   = ty * 128;
    const int w    = tid >> 5, lane = tid & 31;
    const int srl  = tid >> 3;      // compute row within chunk
    const int cc   = tid & 7;       // compute column

    for (int i = tid; i < 512; i += 256) { kws[i] = key_w[i]; vws[i] = value_w[i]; }
    if (tid < 64) { scl[tid] = ln_scale[tid]; bia[tid] = ln_bias[tid]; }
    __syncthreads();

    const float4* kw4 = (const float4*)kws;
    const float4* vw4 = (const float4*)vws;

    float q0 = 0.f, q1 = 0.f, msum = 0.f;   // persistent across chunks

    for (int cs = 0; cs < 4; ++cs) {
        const int sb = s0 + cs * 32;

        // ---- load: 32 rows x 2KB contiguous per row, coalesced ----
#pragma unroll
        for (int round = 0; round < 16; ++round) {
            const int j = round * 256 + tid;         // float4 index, 0..4095
            const int sr = j >> 7, f = j & 127;      // row, float4-in-row
            const float4 t = ((const float4*)(act + ((size_t)(sb + sr) * NRES + r0) * CM))[f];
            *(float4*)(xch + (sr * 8 + (f >> 4)) * RST + (f & 15) * 4) = t;
        }
        mch[tid & 255] = mask[(size_t)(sb + srl) * NRES + r0 + cc];
        __syncthreads();

        // ---- compute: one thread per (s, c) row; LN + K/V, zero shuffles ----
        {
            float4* row4 = (float4*)(xch + (srl * 8 + cc) * RST);
            float sum = 0.f, ss = 0.f;
#pragma unroll
            for (int i = 0; i < 16; i++) {
                const float4 t = row4[i];
                sum += t.x + t.y + t.z + t.w;
                ss  += t.x*t.x + t.y*t.y + t.z*t.z + t.w*t.w;
            }
            const float mu = sum * (1.f / 64.f);
            const float var = ss * (1.f / 64.f) - mu * mu;
            const float rstd = rsqrtf(var + 1e-5f);

            float4 k0 = {0,0,0,0}, k1 = {0,0,0,0}, v0 = {0,0,0,0}, v1 = {0,0,0,0};
#pragma unroll
            for (int i = 0; i < 16; i++) {
                const float4 t = row4[i];
                float4 xn;
                xn.x = (t.x - mu) * rstd * scl[i*4+0] + bia[i*4+0];
                xn.y = (t.y - mu) * rstd * scl[i*4+1] + bia[i*4+1];
                xn.z = (t.z - mu) * rstd * scl[i*4+2] + bia[i*4+2];
                xn.w = (t.w - mu) * rstd * scl[i*4+3] + bia[i*4+3];
                fma4(k0, xn.x, kw4[(i*4+0)*2]); fma4(k1, xn.x, kw4[(i*4+0)*2+1]);
                fma4(v0, xn.x, vw4[(i*4+0)*2]); fma4(v1, xn.x, vw4[(i*4+0)*2+1]);
                fma4(k0, xn.y, kw4[(i*4+1)*2]); fma4(k1, xn.y, kw4[(i*4+1)*2+1]);
                fma4(v0, xn.y, vw4[(i*4+1)*2]); fma4(v1, xn.y, vw4[(i*4+1)*2+1]);
                fma4(k0, xn.z, kw4[(i*4+2)*2]); fma4(k1, xn.z, kw4[(i*4+2)*2+1]);
                fma4(v0, xn.z, vw4[(i*4+2)*2]); fma4(v1, xn.z, vw4[(i*4+2)*2+1]);
                fma4(k0, xn.w, kw4[(i*4+3)*2]); fma4(k1, xn.w, kw4[(i*4+3)*2+1]);
                fma4(v0, xn.w, vw4[(i*4+3)*2]); fma4(v1, xn.w, vw4[(i*4+3)*2+1]);
                row4[i] = xn;   // write xn back in place
            }
            float4* dst = (float4*)(g_kv + ((size_t)(r0 + cc) * NSEQ + sb + srl) * 16);
            dst[0] = k0; dst[1] = k1; dst[2] = v0; dst[3] = v1;
        }
        __syncthreads();

        // ---- qsum pass: warp w owns column w; lane owns channels 2l,2l+1 ----
        for (int sr = 0; sr < 32; ++sr) {
            const float mm = mch[sr * 8 + w];
            const float2 x2 = *(const float2*)(xch + (sr * 8 + w) * RST + 2 * lane);
            q0 += mm * x2.x;  q1 += mm * x2.y;
            if (lane == 0) {} // keep msum uniform below
            msum += (lane == 0 ? mm : 0.f);
        }
        // mask transpose write: coalesced 128B per warp
        g_mskd[(r0 + w) * NSEQ + sb + lane] = mch[lane * 8 + w];
        __syncthreads();
    }

    // lane 0 holds msum; all lanes hold q0/q1 for their channel pair
    *(float2*)(g_qsp + ((size_t)(r0 + w) * 8 + ty) * 64 + 2 * lane) = make_float2(q0, q1);
    if (lane == 0) g_msp[(r0 + w) * 8 + ty] = msum;
}

// ---------------------------------------------------------------------------
// Kernel 1b: softmax attention for one column. grid = 768, 256 threads.
// ---------------------------------------------------------------------------
__global__ void __launch_bounds__(256, 2) msa_k1b(
    const float* __restrict__ query_w)  // [64, 64]
{
    extern __shared__ float sm[];
    float* ks   = sm;              // 8192
    float* vs   = ks + 8192;       // 8192
    float* lsm  = vs + 8192;       // 8192
    float* msk  = lsm + 8192;      // 1024
    float* qsum = msk + 1024;      // 64
    float* qf   = qsum + 64;       // 64
    float* red  = qf + 64;         // 64
    float* gmax = red + 64;        // 8
    float* invZ = gmax + 8;        // 8
    float* part = invZ + 8;        // 256
    float* Msum = part + 256;      // 1   -> 26065 floats

    const int tid  = threadIdx.x;
    const int r    = blockIdx.x;
    const int lane = tid & 31;
    const int w    = tid >> 5;

    // bulk-coalesced k/v load
    const float4* kv4 = (const float4*)(g_kv + (size_t)r * NSEQ * 16);
    float4* ks4 = (float4*)ks;
    float4* vs4 = (float4*)vs;
    for (int i = tid; i < 4096; i += 256) {
        const int s = i >> 2, q = i & 3;
        const float4 v = kv4[i];
        if (q < 2) ks4[s * 2 + q] = v;
        else       vs4[s * 2 + (q - 2)] = v;
    }
    for (int i = tid; i < 1024; i += 256) msk[i] = g_mskd[r * NSEQ + i];
    if (tid < 64) {
        float a = 0.f;
#pragma unroll
        for (int t = 0; t < 8; t++) a += g_qsp[((size_t)r * 8 + t) * 64 + tid];
        qsum[tid] = a;
    }
    if (tid == 64) {
        float a = 0.f;
#pragma unroll
        for (int t = 0; t < 8; t++) a += g_msp[r * 8 + t];
        *Msum = a;
    }
    __syncthreads();

    // q projection
    if (tid < 64) {
        const float invM = 1.f / (*Msum + 1e-10f);
        float acc = 0.f;
        for (int c = 0; c < 64; c++) acc += qsum[c] * query_w[c * 64 + tid];
        qf[tid] = acc * invM * 0.35355339059327373f;
    }
    __syncthreads();

    // logits + max
    float lmax[8];
#pragma unroll
    for (int h = 0; h < 8; h++) lmax[h] = -3.4e38f;
#pragma unroll
    for (int it = 0; it < 4; it++) {
        const int s = tid + it * 256;
        const float4* kp = (const float4*)(ks + s * 8);
        const float4 k0 = kp[0], k1 = kp[1];
        const float b = 1e9f * (msk[s] - 1.f);
#pragma unroll
        for (int h = 0; h < 8; h++) {
            const float* q = qf + h * 8;
            float l = b + q[0]*k0.x + q[1]*k0.y + q[2]*k0.z + q[3]*k0.w
                        + q[4]*k1.x + q[5]*k1.y + q[6]*k1.z + q[7]*k1.w;
            lsm[s * 8 + h] = l;
            lmax[h] = fmaxf(lmax[h], l);
        }
    }
#pragma unroll
    for (int h = 0; h < 8; h++) {
#pragma unroll
        for (int off = 16; off; off >>= 1)
            lmax[h] = fmaxf(lmax[h], __shfl_xor_sync(0xffffffffu, lmax[h], off));
    }
    if (lane == 0) {
#pragma unroll
        for (int h = 0; h < 8; h++) red[w * 8 + h] = lmax[h];
    }
    __syncthreads();
    if (tid < 8) {
        float mm = red[tid];
#pragma unroll
        for (int ww = 1; ww < 8; ww++) mm = fmaxf(mm, red[ww * 8 + tid]);
        gmax[tid] = mm;
    }
    __syncthreads();

    // exp + Z
    float zl[8];
#pragma unroll
    for (int h = 0; h < 8; h++) zl[h] = 0.f;
#pragma unroll
    for (int it = 0; it < 4; it++) {
        const int s = tid + it * 256;
#pragma unroll
        for (int h = 0; h < 8; h++) {
            const float e = __expf(lsm[s * 8 + h] - gmax[h]);
            lsm[s * 8 + h] = e;
            zl[h] += e;
        }
    }
#pragma unroll
    for (int h = 0; h < 8; h++) {
#pragma unroll
        for (int off = 16; off; off >>= 1)
            zl[h] += __shfl_xor_sync(0xffffffffu, zl[h], off);
    }
    if (lane == 0) {
#pragma unroll
        for (int h = 0; h < 8; h++) red[w * 8 + h] = zl[h];
    }
    __syncthreads();
    if (tid < 8) {
        float z = 0.f;
#pragma unroll
        for (int ww = 0; ww < 8; ww++) z += red[ww * 8 + tid];
        invZ[tid] = 1.f / z;
    }
    __syncthreads();

    // weighted_avg
    {
        const int hd = tid & 63, q4 = tid >> 6;
        const int h = hd >> 3, d = hd & 7;
        float p = 0.f;
        const int sb = q4 * 256;
        for (int s = sb; s < sb + 256; ++s)
            p += lsm[s * 8 + h] * vs[s * 8 + d];
        part[tid] = p;
    }
    __syncthreads();
    if (tid < 64) {
        const int h = tid >> 3;
        g_wa[r * 64 + tid] =
            (part[tid] + part[tid + 64] + part[tid + 128] + part[tid + 192]) * invZ[h];
    }
}

// ---------------------------------------------------------------------------
// Kernel 2: gate + output via tf32 MMA (proven 196 us version, unchanged).
// ---------------------------------------------------------------------------
#define XS 68

__global__ void __launch_bounds__(256, 2) msa_k2(
    const float* __restrict__ act,
    const float* __restrict__ ln_scale, const float* __restrict__ ln_bias,
    const float* __restrict__ gating_w,  // [64, 64]
    const float* __restrict__ gating_b,  // [64]
    const float* __restrict__ output_w,  // [64, 64]
    const float* __restrict__ output_b,  // [64]
    float* __restrict__ out)             // [S, R, C]
{
    extern __shared__ float sm2[];
    float* xnf = sm2;              // 256 rows * 68 = 17408
    float* gwf = xnf + 17408;      // 4096
    float* owf = gwf + 4096;       // 4096
    float* was = owf + 4096;       // 64
    float* gbs = was + 64;         // 64
    float* obs = gbs + 64;         // 64
    float* scl = obs + 64;         // 64
    float* bia = scl + 64;         // 64

    const int tid  = threadIdx.x;
    const int r    = blockIdx.x;
    const int s0   = blockIdx.y * 256;
    const int w    = tid >> 5, lane = tid & 31;
    const int c4   = lane & 15, rsel = lane >> 4;
    const int g    = lane >> 2, t = lane & 3;

    for (int i = tid; i < 4096; i += 256) {
        const int c = i >> 6, j = i & 63;
        const int kk = c >> 3, tt = c & 7;
        const int nn = j >> 3, gg = j & 7;
        const int off = ((nn * 8 + kk) * 32 + gg * 4 + (tt & 3)) * 2 + (tt >> 2);
        gwf[off] = __uint_as_float(f2tf32(gating_w[i]));
        owf[off] = __uint_as_float(f2tf32(output_w[i]));
    }
    if (tid < 64) {
        was[tid] = g_wa[r * 64 + tid];
        gbs[tid] = gating_b[tid];  obs[tid] = output_b[tid];
        scl[tid] = ln_scale[tid];  bia[tid] = ln_bias[tid];
    }
    __syncthreads();

    {
        const float4 sc = ((const float4*)scl)[c4];
        const float4 bi = ((const float4*)bia)[c4];
#pragma unroll
        for (int rnd = 0; rnd < 16; rnd++) {
            const int row = w * 32 + rnd * 2 + rsel;
            const float4 tt = *(const float4*)(act + ((size_t)(s0 + row) * NRES + r) * CM + c4 * 4);
            float sum = tt.x + tt.y + tt.z + tt.w;
            sum += __shfl_xor_sync(0xffffffffu, sum, 1);
            sum += __shfl_xor_sync(0xffffffffu, sum, 2);
            sum += __shfl_xor_sync(0xffffffffu, sum, 4);
            sum += __shfl_xor_sync(0xffffffffu, sum, 8);
            const float mu = sum * (1.f / 64.f);
            float vv = (tt.x-mu)*(tt.x-mu) + (tt.y-mu)*(tt.y-mu)
                     + (tt.z-mu)*(tt.z-mu) + (tt.w-mu)*(tt.w-mu);
            vv += __shfl_xor_sync(0xffffffffu, vv, 1);
            vv += __shfl_xor_sync(0xffffffffu, vv, 2);
            vv += __shfl_xor_sync(0xffffffffu, vv, 4);
            vv += __shfl_xor_sync(0xffffffffu, vv, 8);
            const float rstd = rsqrtf(vv * (1.f / 64.f) + 1e-5f);
            float4 o;
            o.x = __uint_as_float(f2tf32((tt.x - mu) * rstd * sc.x + bi.x));
            o.y = __uint_as_float(f2tf32((tt.y - mu) * rstd * sc.y + bi.y));
            o.z = __uint_as_float(f2tf32((tt.z - mu) * rstd * sc.z + bi.z));
            o.w = __uint_as_float(f2tf32((tt.w - mu) * rstd * sc.w + bi.w));
            *(float4*)(xnf + row * XS + c4 * 4) = o;
        }
    }
    __syncwarp();

    const int rb = w * 32;
    float* st0 = xnf + rb * XS;
    float* st1 = xnf + (rb + 16) * XS;

    float4 acc0[8], acc1[8];
#pragma unroll
    for (int n = 0; n < 8; n++) { acc0[n] = make_float4(0,0,0,0); acc1[n] = make_float4(0,0,0,0); }
#pragma unroll
    for (int k = 0; k < 8; k++) {
        const int kc = k * 8 + t;
        const uint32_t a00 = __float_as_uint(st0[g * XS + kc]);
        const uint32_t a01 = __float_as_uint(st0[(g + 8) * XS + kc]);
        const uint32_t a02 = __float_as_uint(st0[g * XS + kc + 4]);
        const uint32_t a03 = __float_as_uint(st0[(g + 8) * XS + kc + 4]);
        const uint32_t a10 = __float_as_uint(st1[g * XS + kc]);
        const uint32_t a11 = __float_as_uint(st1[(g + 8) * XS + kc]);
        const uint32_t a12 = __float_as_uint(st1[g * XS + kc + 4]);
        const uint32_t a13 = __float_as_uint(st1[(g + 8) * XS + kc + 4]);
#pragma unroll
        for (int n = 0; n < 8; n++) {
            const float2 b = *(const float2*)(gwf + ((n * 8 + k) * 32 + lane) * 2);
            mma_tf32(acc0[n], a00, a01, a02, a03,
                     __float_as_uint(b.x), __float_as_uint(b.y));
            mma_tf32(acc1[n], a10, a11, a12, a13,
                     __float_as_uint(b.x), __float_as_uint(b.y));
        }
    }
    __syncwarp();

#pragma unroll
    for (int n = 0; n < 8; n++) {
        const int c0 = n * 8 + 2 * t;
        const float w0 = was[c0], w1 = was[c0 + 1];
        const float b0 = gbs[c0], b1 = gbs[c0 + 1];
        float2 p;
        p.x = __uint_as_float(f2tf32(w0 * sigf(acc0[n].x + b0)));
        p.y = __uint_as_float(f2tf32(w1 * sigf(acc0[n].y + b1)));
        *(float2*)(st0 + g * XS + c0) = p;
        p.x = __uint_as_float(f2tf32(w0 * sigf(acc0[n].z + b0)));
        p.y = __uint_as_float(f2tf32(w1 * sigf(acc0[n].w + b1)));
        *(float2*)(st0 + (g + 8) * XS + c0) = p;
        p.x = __uint_as_float(f2tf32(w0 * sigf(acc1[n].x + b0)));
        p.y = __uint_as_float(f2tf32(w1 * sigf(acc1[n].y + b1)));
        *(float2*)(st1 + g * XS + c0) = p;
        p.x = __uint_as_float(f2tf32(w0 * sigf(acc1[n].z + b0)));
        p.y = __uint_as_float(f2tf32(w1 * sigf(acc1[n].w + b1)));
        *(float2*)(st1 + (g + 8) * XS + c0) = p;
    }
    __syncwarp();

    float4 o0[8], o1[8];
#pragma unroll
    for (int n = 0; n < 8; n++) {
        const int c0 = n * 8 + 2 * t;
        o0[n] = make_float4(obs[c0], obs[c0+1], obs[c0], obs[c0+1]);
        o1[n] = o0[n];
    }
#pragma unroll
    for (int k = 0; k < 8; k++) {
        const int kc = k * 8 + t;
        const uint32_t a00 = __float_as_uint(st0[g * XS + kc]);
        const uint32_t a01 = __float_as_uint(st0[(g + 8) * XS + kc]);
        const uint32_t a02 = __float_as_uint(st0[g * XS + kc + 4]);
        const uint32_t a03 = __float_as_uint(st0[(g + 8) * XS + kc + 4]);
        const uint32_t a10 = __float_as_uint(st1[g * XS + kc]);
        const uint32_t a11 = __float_as_uint(st1[(g + 8) * XS + kc]);
        const uint32_t a12 = __float_as_uint(st1[g * XS + kc + 4]);
        const uint32_t a13 = __float_as_uint(st1[(g + 8) * XS + kc + 4]);
#pragma unroll
        for (int n = 0; n < 8; n++) {
            const float2 b = *(const float2*)(owf + ((n * 8 + k) * 32 + lane) * 2);
            mma_tf32(o0[n], a00, a01, a02, a03,
                     __float_as_uint(b.x), __float_as_uint(b.y));
            mma_tf32(o1[n], a10, a11, a12, a13,
                     __float_as_uint(b.x), __float_as_uint(b.y));
        }
    }
    __syncwarp();

#pragma unroll
    for (int n = 0; n < 8; n++) {
        const int c0 = n * 8 + 2 * t;
        *(float2*)(st0 + g * XS + c0)       = make_float2(o0[n].x, o0[n].y);
        *(float2*)(st0 + (g + 8) * XS + c0) = make_float2(o0[n].z, o0[n].w);
        *(float2*)(st1 + g * XS + c0)       = make_float2(o1[n].x, o1[n].y);
        *(float2*)(st1 + (g + 8) * XS + c0) = make_float2(o1[n].z, o1[n].w);
    }
    __syncwarp();

#pragma unroll
    for (int rnd = 0; rnd < 16; rnd++) {
        const int row = w * 32 + rnd * 2 + rsel;
        const float4 v = *(const float4*)(xnf + row * XS + c4 * 4);
        *(float4*)(out + ((size_t)(s0 + row) * NRES + r) * CM + c4 * 4) = v;
    }
}

// ---------------------------------------------------------------------------
#define K1A_SMEM (18816 * 4)
#define K1B_SMEM (26065 * 4)
#define K2_SMEM  (25920 * 4)

extern "C" void kernel_launch(void* const* d_in, const int* in_sizes, int n_in,
                              void* d_out, int out_size) {
    (void)in_sizes; (void)n_in; (void)out_size;
    const float* act      = (const float*)d_in[0];
    const float* mask     = (const float*)d_in[1];
    const float* ln_scale = (const float*)d_in[2];
    const float* ln_bias  = (const float*)d_in[3];
    const float* query_w  = (const float*)d_in[4];
    const float* key_w    = (const float*)d_in[5];
    const float* value_w  = (const float*)d_in[6];
    const float* gating_w = (const float*)d_in[7];
    const float* gating_b = (const float*)d_in[8];
    const float* output_w = (const float*)d_in[9];
    const float* output_b = (const float*)d_in[10];
    float* out = (float*)d_out;

    cudaFuncSetAttribute(msa_k1a, cudaFuncAttributeMaxDynamicSharedMemorySize, K1A_SMEM);
    cudaFuncSetAttribute(msa_k1b, cudaFuncAttributeMaxDynamicSharedMemorySize, K1B_SMEM);
    cudaFuncSetAttribute(msa_k2,  cudaFuncAttributeMaxDynamicSharedMemorySize, K2_SMEM);

    msa_k1a<<<dim3(96, 8), 256, K1A_SMEM>>>(act, mask, ln_scale, ln_bias, key_w, value_w);
    msa_k1b<<<NRES, 256, K1B_SMEM>>>(query_w);
    msa_k2<<<dim3(NRES, 4), 256, K2_SMEM>>>(act, ln_scale, ln_bias,
                                            gating_w, gating_b, output_w, output_b, out);
}

// round 10
// speedup vs baseline: 3.3316x; 1.0621x over previous
#include <cuda_runtime.h>
#include <cstdint>

#define NSEQ 1024
#define NRES 768
#define CM   64

// scratch
__device__ float g_wa[NRES * CM];                // weighted_avg per column
__device__ float g_kv[(size_t)NRES * NSEQ * 16]; // [r][s][0..7]=k, [8..15]=v
__device__ float g_xn[(size_t)NSEQ * NRES * CM]; // tf32-rounded LN(act), [S,R,C]
__device__ float g_mskd[NRES * NSEQ];            // mask transposed [r][s]
__device__ float g_qsp[NRES * 8 * 64];           // partial masked sums per s-tile
__device__ float g_msp[NRES * 8];                // partial mask sums per s-tile

__device__ __forceinline__ void fma4(float4& a, float s, const float4 w) {
    a.x += s * w.x; a.y += s * w.y; a.z += s * w.z; a.w += s * w.w;
}
__device__ __forceinline__ uint32_t f2tf32(float f) {
    uint32_t r;
    asm("cvt.rna.tf32.f32 %0, %1;" : "=r"(r) : "f"(f));
    return r;
}
__device__ __forceinline__ void mma_tf32(float4& d,
    uint32_t a0, uint32_t a1, uint32_t a2, uint32_t a3,
    uint32_t b0, uint32_t b1) {
    asm volatile("mma.sync.aligned.m16n8k8.row.col.f32.tf32.tf32.f32 "
        "{%0,%1,%2,%3}, {%4,%5,%6,%7}, {%8,%9}, {%0,%1,%2,%3};"
        : "+f"(d.x), "+f"(d.y), "+f"(d.z), "+f"(d.w)
        : "r"(a0), "r"(a1), "r"(a2), "r"(a3), "r"(b0), "r"(b1));
}
__device__ __forceinline__ float sigf(float x) {
    return __fdividef(1.f, 1.f + __expf(-x));
}
__device__ __forceinline__ uint32_t su32(const void* p) {
    return (uint32_t)__cvta_generic_to_shared(p);
}
__device__ __forceinline__ void cpasync16(uint32_t dst, const void* src) {
    asm volatile("cp.async.cg.shared.global [%0], [%1], 16;" :: "r"(dst), "l"(src));
}
#define CP_COMMIT() asm volatile("cp.async.commit_group;")
#define CP_WAIT0()  asm volatile("cp.async.wait_group 0;")

// ---------------------------------------------------------------------------
// Kernel 1a: LN + K/V projection + XN writeback. Block = 8 cols x 128 rows.
// grid = (96, 8), 256 threads, occupancy 2. cp.async staging.
// ---------------------------------------------------------------------------
#define RST 68

__global__ void __launch_bounds__(256, 2) msa_k1a(
    const float* __restrict__ act,      // [S, R, C]
    const float* __restrict__ mask,     // [S, R]
    const float* __restrict__ ln_scale, const float* __restrict__ ln_bias,
    const float* __restrict__ key_w,    // [64, 8]
    const float* __restrict__ value_w)  // [64, 8]
{
    extern __shared__ float smk[];
    float* xch = smk;            // 32*8*68 = 17408 : x -> xn(tf32) in place
    float* mch = xch + 17408;    // 256
    float* kws = mch + 256;      // 512
    float* vws = kws + 512;      // 512
    float* scl = vws + 512;      // 64
    float* bia = scl + 64;       // 64

    const int tid  = threadIdx.x;
    const int r0   = blockIdx.x * 8;
    const int ty   = blockIdx.y;
    const int s0   = ty * 128;
    const int w    = tid >> 5, lane = tid & 31;
    const int srl  = tid >> 3;      // compute row within chunk
    const int cc   = tid & 7;       // compute column

    for (int i = tid; i < 512; i += 256) { kws[i] = key_w[i]; vws[i] = value_w[i]; }
    if (tid < 64) { scl[tid] = ln_scale[tid]; bia[tid] = ln_bias[tid]; }
    __syncthreads();

    const float4* kw4 = (const float4*)kws;
    const float4* vw4 = (const float4*)vws;
    const uint32_t xba = su32(xch);

    float q0 = 0.f, q1 = 0.f, msum = 0.f;

    for (int cs = 0; cs < 4; ++cs) {
        const int sb = s0 + cs * 32;

        // ---- stage via cp.async: 32 rows x 2KB contiguous ----
#pragma unroll
        for (int round = 0; round < 16; ++round) {
            const int j = round * 256 + tid;
            const int sr = j >> 7, f = j & 127;
            cpasync16(xba + ((sr * 8 + (f >> 4)) * RST + (f & 15) * 4) * 4,
                      act + ((size_t)(sb + sr) * NRES + r0) * CM + f * 4);
        }
        CP_COMMIT();
        mch[tid] = mask[(size_t)(sb + srl) * NRES + r0 + cc];
        CP_WAIT0();
        __syncthreads();

        // ---- compute: one thread per (s,c) row; LN + K/V; zero shuffles ----
        {
            float4* row4 = (float4*)(xch + (srl * 8 + cc) * RST);
            float sum = 0.f, ss = 0.f;
#pragma unroll
            for (int i = 0; i < 16; i++) {
                const float4 t = row4[i];
                sum += t.x + t.y + t.z + t.w;
                ss  += t.x*t.x + t.y*t.y + t.z*t.z + t.w*t.w;
            }
            const float mu = sum * (1.f / 64.f);
            const float var = ss * (1.f / 64.f) - mu * mu;
            const float rstd = rsqrtf(var + 1e-5f);

            float4 k0 = {0,0,0,0}, k1 = {0,0,0,0}, v0 = {0,0,0,0}, v1 = {0,0,0,0};
#pragma unroll
            for (int i = 0; i < 16; i++) {
                const float4 t = row4[i];
                float4 xn;
                xn.x = (t.x - mu) * rstd * scl[i*4+0] + bia[i*4+0];
                xn.y = (t.y - mu) * rstd * scl[i*4+1] + bia[i*4+1];
                xn.z = (t.z - mu) * rstd * scl[i*4+2] + bia[i*4+2];
                xn.w = (t.w - mu) * rstd * scl[i*4+3] + bia[i*4+3];
                fma4(k0, xn.x, kw4[(i*4+0)*2]); fma4(k1, xn.x, kw4[(i*4+0)*2+1]);
                fma4(v0, xn.x, vw4[(i*4+0)*2]); fma4(v1, xn.x, vw4[(i*4+0)*2+1]);
                fma4(k0, xn.y, kw4[(i*4+1)*2]); fma4(k1, xn.y, kw4[(i*4+1)*2+1]);
                fma4(v0, xn.y, vw4[(i*4+1)*2]); fma4(v1, xn.y, vw4[(i*4+1)*2+1]);
                fma4(k0, xn.z, kw4[(i*4+2)*2]); fma4(k1, xn.z, kw4[(i*4+2)*2+1]);
                fma4(v0, xn.z, vw4[(i*4+2)*2]); fma4(v1, xn.z, vw4[(i*4+2)*2+1]);
                fma4(k0, xn.w, kw4[(i*4+3)*2]); fma4(k1, xn.w, kw4[(i*4+3)*2+1]);
                fma4(v0, xn.w, vw4[(i*4+3)*2]); fma4(v1, xn.w, vw4[(i*4+3)*2+1]);
                // write back tf32-rounded xn
                xn.x = __uint_as_float(f2tf32(xn.x));
                xn.y = __uint_as_float(f2tf32(xn.y));
                xn.z = __uint_as_float(f2tf32(xn.z));
                xn.w = __uint_as_float(f2tf32(xn.w));
                row4[i] = xn;
            }
            float4* dst = (float4*)(g_kv + ((size_t)(r0 + cc) * NSEQ + sb + srl) * 16);
            dst[0] = k0; dst[1] = k1; dst[2] = v0; dst[3] = v1;
        }
        __syncthreads();

        // ---- XN writeback: coalesced 2KB rows ----
#pragma unroll
        for (int round = 0; round < 16; ++round) {
            const int j = round * 256 + tid;
            const int sr = j >> 7, f = j & 127;
            const float4 t = *(const float4*)(xch + (sr * 8 + (f >> 4)) * RST + (f & 15) * 4);
            ((float4*)(g_xn + ((size_t)(sb + sr) * NRES + r0) * CM))[f] = t;
        }

        // ---- qsum pass: warp w owns column w; lane owns channels 2l,2l+1 ----
        for (int sr = 0; sr < 32; ++sr) {
            const float mm = mch[sr * 8 + w];
            const float2 x2 = *(const float2*)(xch + (sr * 8 + w) * RST + 2 * lane);
            q0 += mm * x2.x;  q1 += mm * x2.y;
            msum += (lane == 0 ? mm : 0.f);
        }
        g_mskd[(r0 + w) * NSEQ + sb + lane] = mch[lane * 8 + w];
        __syncthreads();
    }

    *(float2*)(g_qsp + ((size_t)(r0 + w) * 8 + ty) * 64 + 2 * lane) = make_float2(q0, q1);
    if (lane == 0) g_msp[(r0 + w) * 8 + ty] = msum;
}

// ---------------------------------------------------------------------------
// Kernel 1b: softmax attention for one column. grid = 768, 256 threads.
// ---------------------------------------------------------------------------
__global__ void __launch_bounds__(256, 2) msa_k1b(
    const float* __restrict__ query_w)  // [64, 64]
{
    extern __shared__ float sm[];
    float* ks   = sm;              // 8192
    float* vs   = ks + 8192;       // 8192
    float* lsm  = vs + 8192;       // 8192
    float* msk  = lsm + 8192;      // 1024
    float* qsum = msk + 1024;      // 64
    float* qf   = qsum + 64;       // 64
    float* red  = qf + 64;         // 64
    float* gmax = red + 64;        // 8
    float* invZ = gmax + 8;        // 8
    float* part = invZ + 8;        // 256
    float* Msum = part + 256;      // 1   -> 26065 floats

    const int tid  = threadIdx.x;
    const int r    = blockIdx.x;
    const int lane = tid & 31;
    const int w    = tid >> 5;

    const float4* kv4 = (const float4*)(g_kv + (size_t)r * NSEQ * 16);
    float4* ks4 = (float4*)ks;
    float4* vs4 = (float4*)vs;
    for (int i = tid; i < 4096; i += 256) {
        const int s = i >> 2, q = i & 3;
        const float4 v = kv4[i];
        if (q < 2) ks4[s * 2 + q] = v;
        else       vs4[s * 2 + (q - 2)] = v;
    }
    for (int i = tid; i < 1024; i += 256) msk[i] = g_mskd[r * NSEQ + i];
    if (tid < 64) {
        float a = 0.f;
#pragma unroll
        for (int t = 0; t < 8; t++) a += g_qsp[((size_t)r * 8 + t) * 64 + tid];
        qsum[tid] = a;
    }
    if (tid == 64) {
        float a = 0.f;
#pragma unroll
        for (int t = 0; t < 8; t++) a += g_msp[r * 8 + t];
        *Msum = a;
    }
    __syncthreads();

    if (tid < 64) {
        const float invM = 1.f / (*Msum + 1e-10f);
        float acc = 0.f;
        for (int c = 0; c < 64; c++) acc += qsum[c] * query_w[c * 64 + tid];
        qf[tid] = acc * invM * 0.35355339059327373f;
    }
    __syncthreads();

    float lmax[8];
#pragma unroll
    for (int h = 0; h < 8; h++) lmax[h] = -3.4e38f;
#pragma unroll
    for (int it = 0; it < 4; it++) {
        const int s = tid + it * 256;
        const float4* kp = (const float4*)(ks + s * 8);
        const float4 k0 = kp[0], k1 = kp[1];
        const float b = 1e9f * (msk[s] - 1.f);
#pragma unroll
        for (int h = 0; h < 8; h++) {
            const float* q = qf + h * 8;
            float l = b + q[0]*k0.x + q[1]*k0.y + q[2]*k0.z + q[3]*k0.w
                        + q[4]*k1.x + q[5]*k1.y + q[6]*k1.z + q[7]*k1.w;
            lsm[s * 8 + h] = l;
            lmax[h] = fmaxf(lmax[h], l);
        }
    }
#pragma unroll
    for (int h = 0; h < 8; h++) {
#pragma unroll
        for (int off = 16; off; off >>= 1)
            lmax[h] = fmaxf(lmax[h], __shfl_xor_sync(0xffffffffu, lmax[h], off));
    }
    if (lane == 0) {
#pragma unroll
        for (int h = 0; h < 8; h++) red[w * 8 + h] = lmax[h];
    }
    __syncthreads();
    if (tid < 8) {
        float mm = red[tid];
#pragma unroll
        for (int ww = 1; ww < 8; ww++) mm = fmaxf(mm, red[ww * 8 + tid]);
        gmax[tid] = mm;
    }
    __syncthreads();

    float zl[8];
#pragma unroll
    for (int h = 0; h < 8; h++) zl[h] = 0.f;
#pragma unroll
    for (int it = 0; it < 4; it++) {
        const int s = tid + it * 256;
#pragma unroll
        for (int h = 0; h < 8; h++) {
            const float e = __expf(lsm[s * 8 + h] - gmax[h]);
            lsm[s * 8 + h] = e;
            zl[h] += e;
        }
    }
#pragma unroll
    for (int h = 0; h < 8; h++) {
#pragma unroll
        for (int off = 16; off; off >>= 1)
            zl[h] += __shfl_xor_sync(0xffffffffu, zl[h], off);
    }
    if (lane == 0) {
#pragma unroll
        for (int h = 0; h < 8; h++) red[w * 8 + h] = zl[h];
    }
    __syncthreads();
    if (tid < 8) {
        float z = 0.f;
#pragma unroll
        for (int ww = 0; ww < 8; ww++) z += red[ww * 8 + tid];
        invZ[tid] = 1.f / z;
    }
    __syncthreads();

    {
        const int hd = tid & 63, q4 = tid >> 6;
        const int h = hd >> 3, d = hd & 7;
        float p = 0.f;
        const int sb = q4 * 256;
        for (int s = sb; s < sb + 256; ++s)
            p += lsm[s * 8 + h] * vs[s * 8 + d];
        part[tid] = p;
    }
    __syncthreads();
    if (tid < 64) {
        const int h = tid >> 3;
        g_wa[r * 64 + tid] =
            (part[tid] + part[tid + 64] + part[tid + 128] + part[tid + 192]) * invZ[h];
    }
}

// ---------------------------------------------------------------------------
// Kernel 2: gate + output via tf32 MMA. No LN — reads precomputed g_xn via
// cp.async. grid = (768, 4 tiles of 256 rows), 256 threads.
// ---------------------------------------------------------------------------
#define XS 68

__global__ void __launch_bounds__(256, 2) msa_k2(
    const float* __restrict__ gating_w,  // [64, 64]
    const float* __restrict__ gating_b,  // [64]
    const float* __restrict__ output_w,  // [64, 64]
    const float* __restrict__ output_b,  // [64]
    float* __restrict__ out)             // [S, R, C]
{
    extern __shared__ float sm2[];
    float* xnf = sm2;              // 256 rows * 68 = 17408
    float* gwf = xnf + 17408;      // 4096
    float* owf = gwf + 4096;       // 4096
    float* was = owf + 4096;       // 64
    float* gbs = was + 64;         // 64
    float* obs = gbs + 64;         // 64

    const int tid  = threadIdx.x;
    const int r    = blockIdx.x;
    const int s0   = blockIdx.y * 256;
    const int w    = tid >> 5, lane = tid & 31;
    const int c4   = lane & 15, rsel = lane >> 4;
    const int g    = lane >> 2, t = lane & 3;

    // ---- stage xn tile via cp.async (no LN here) ----
    const uint32_t xba = su32(xnf);
#pragma unroll
    for (int rnd = 0; rnd < 16; rnd++) {
        const int j = rnd * 256 + tid;        // float4 idx 0..4095
        const int row = j >> 4, f = j & 15;
        cpasync16(xba + (row * XS + f * 4) * 4,
                  g_xn + ((size_t)(s0 + row) * NRES + r) * CM + f * 4);
    }
    CP_COMMIT();

    // ---- stage weights into B-fragment layout (overlaps cp.async) ----
    for (int i = tid; i < 4096; i += 256) {
        const int c = i >> 6, j = i & 63;
        const int kk = c >> 3, tt = c & 7;
        const int nn = j >> 3, gg = j & 7;
        const int off = ((nn * 8 + kk) * 32 + gg * 4 + (tt & 3)) * 2 + (tt >> 2);
        gwf[off] = __uint_as_float(f2tf32(gating_w[i]));
        owf[off] = __uint_as_float(f2tf32(output_w[i]));
    }
    if (tid < 64) {
        was[tid] = g_wa[r * 64 + tid];
        gbs[tid] = gating_b[tid];  obs[tid] = output_b[tid];
    }
    CP_WAIT0();
    __syncthreads();

    const int rb = w * 32;
    float* st0 = xnf + rb * XS;
    float* st1 = xnf + (rb + 16) * XS;

    // ---- GEMM1: logits = XN @ GW ----
    float4 acc0[8], acc1[8];
#pragma unroll
    for (int n = 0; n < 8; n++) { acc0[n] = make_float4(0,0,0,0); acc1[n] = make_float4(0,0,0,0); }
#pragma unroll
    for (int k = 0; k < 8; k++) {
        const int kc = k * 8 + t;
        const uint32_t a00 = __float_as_uint(st0[g * XS + kc]);
        const uint32_t a01 = __float_as_uint(st0[(g + 8) * XS + kc]);
        const uint32_t a02 = __float_as_uint(st0[g * XS + kc + 4]);
        const uint32_t a03 = __float_as_uint(st0[(g + 8) * XS + kc + 4]);
        const uint32_t a10 = __float_as_uint(st1[g * XS + kc]);
        const uint32_t a11 = __float_as_uint(st1[(g + 8) * XS + kc]);
        const uint32_t a12 = __float_as_uint(st1[g * XS + kc + 4]);
        const uint32_t a13 = __float_as_uint(st1[(g + 8) * XS + kc + 4]);
#pragma unroll
        for (int n = 0; n < 8; n++) {
            const float2 b = *(const float2*)(gwf + ((n * 8 + k) * 32 + lane) * 2);
            mma_tf32(acc0[n], a00, a01, a02, a03,
                     __float_as_uint(b.x), __float_as_uint(b.y));
            mma_tf32(acc1[n], a10, a11, a12, a13,
                     __float_as_uint(b.x), __float_as_uint(b.y));
        }
    }
    __syncwarp();

    // ---- gate: G = wa*sigmoid(logit+gb) ----
#pragma unroll
    for (int n = 0; n < 8; n++) {
        const int c0 = n * 8 + 2 * t;
        const float w0 = was[c0], w1 = was[c0 + 1];
        const float b0 = gbs[c0], b1 = gbs[c0 + 1];
        float2 p;
        p.x = __uint_as_float(f2tf32(w0 * sigf(acc0[n].x + b0)));
        p.y = __uint_as_float(f2tf32(w1 * sigf(acc0[n].y + b1)));
        *(float2*)(st0 + g * XS + c0) = p;
        p.x = __uint_as_float(f2tf32(w0 * sigf(acc0[n].z + b0)));
        p.y = __uint_as_float(f2tf32(w1 * sigf(acc0[n].w + b1)));
        *(float2*)(st0 + (g + 8) * XS + c0) = p;
        p.x = __uint_as_float(f2tf32(w0 * sigf(acc1[n].x + b0)));
        p.y = __uint_as_float(f2tf32(w1 * sigf(acc1[n].y + b1)));
        *(float2*)(st1 + g * XS + c0) = p;
        p.x = __uint_as_float(f2tf32(w0 * sigf(acc1[n].z + b0)));
        p.y = __uint_as_float(f2tf32(w1 * sigf(acc1[n].w + b1)));
        *(float2*)(st1 + (g + 8) * XS + c0) = p;
    }
    __syncwarp();

    // ---- GEMM2: OUT = G @ OW + ob ----
    float4 o0[8], o1[8];
#pragma unroll
    for (int n = 0; n < 8; n++) {
        const int c0 = n * 8 + 2 * t;
        o0[n] = make_float4(obs[c0], obs[c0+1], obs[c0], obs[c0+1]);
        o1[n] = o0[n];
    }
#pragma unroll
    for (int k = 0; k < 8; k++) {
        const int kc = k * 8 + t;
        const uint32_t a00 = __float_as_uint(st0[g * XS + kc]);
        const uint32_t a01 = __float_as_uint(st0[(g + 8) * XS + kc]);
        const uint32_t a02 = __float_as_uint(st0[g * XS + kc + 4]);
        const uint32_t a03 = __float_as_uint(st0[(g + 8) * XS + kc + 4]);
        const uint32_t a10 = __float_as_uint(st1[g * XS + kc]);
        const uint32_t a11 = __float_as_uint(st1[(g + 8) * XS + kc]);
        const uint32_t a12 = __float_as_uint(st1[g * XS + kc + 4]);
        const uint32_t a13 = __float_as_uint(st1[(g + 8) * XS + kc + 4]);
#pragma unroll
        for (int n = 0; n < 8; n++) {
            const float2 b = *(const float2*)(owf + ((n * 8 + k) * 32 + lane) * 2);
            mma_tf32(o0[n], a00, a01, a02, a03,
                     __float_as_uint(b.x), __float_as_uint(b.y));
            mma_tf32(o1[n], a10, a11, a12, a13,
                     __float_as_uint(b.x), __float_as_uint(b.y));
        }
    }
    __syncwarp();

    // ---- stage outputs row-major ----
#pragma unroll
    for (int n = 0; n < 8; n++) {
        const int c0 = n * 8 + 2 * t;
        *(float2*)(st0 + g * XS + c0)       = make_float2(o0[n].x, o0[n].y);
        *(float2*)(st0 + (g + 8) * XS + c0) = make_float2(o0[n].z, o0[n].w);
        *(float2*)(st1 + g * XS + c0)       = make_float2(o1[n].x, o1[n].y);
        *(float2*)(st1 + (g + 8) * XS + c0) = make_float2(o1[n].z, o1[n].w);
    }
    __syncwarp();

    // ---- coalesced STG ----
#pragma unroll
    for (int rnd = 0; rnd < 16; rnd++) {
        const int row = w * 32 + rnd * 2 + rsel;
        const float4 v = *(const float4*)(xnf + row * XS + c4 * 4);
        *(float4*)(out + ((size_t)(s0 + row) * NRES + r) * CM + c4 * 4) = v;
    }
}

// ---------------------------------------------------------------------------
#define K1A_SMEM (18816 * 4)
#define K1B_SMEM (26065 * 4)
#define K2_SMEM  (25792 * 4)

extern "C" void kernel_launch(void* const* d_in, const int* in_sizes, int n_in,
                              void* d_out, int out_size) {
    (void)in_sizes; (void)n_in; (void)out_size;
    const float* act      = (const float*)d_in[0];
    const float* mask     = (const float*)d_in[1];
    const float* ln_scale = (const float*)d_in[2];
    const float* ln_bias  = (const float*)d_in[3];
    const float* query_w  = (const float*)d_in[4];
    const float* key_w    = (const float*)d_in[5];
    const float* value_w  = (const float*)d_in[6];
    const float* gating_w = (const float*)d_in[7];
    const float* gating_b = (const float*)d_in[8];
    const float* output_w = (const float*)d_in[9];
    const float* output_b = (const float*)d_in[10];
    float* out = (float*)d_out;

    cudaFuncSetAttribute(msa_k1a, cudaFuncAttributeMaxDynamicSharedMemorySize, K1A_SMEM);
    cudaFuncSetAttribute(msa_k1b, cudaFuncAttributeMaxDynamicSharedMemorySize, K1B_SMEM);
    cudaFuncSetAttribute(msa_k2,  cudaFuncAttributeMaxDynamicSharedMemorySize, K2_SMEM);

    msa_k1a<<<dim3(96, 8), 256, K1A_SMEM>>>(act, mask, ln_scale, ln_bias, key_w, value_w);
    msa_k1b<<<NRES, 256, K1B_SMEM>>>(query_w);
    msa_k2<<<dim3(NRES, 4), 256, K2_SMEM>>>(gating_w, gating_b, output_w, output_b, out);
}

// round 12
// speedup vs baseline: 3.8482x; 1.1551x over previous
#include <cuda_runtime.h>
#include <cstdint>

#define NSEQ 1024
#define NRES 768
#define CM   64

// scratch
__device__ float g_wa[NRES * CM];                // weighted_avg per column
__device__ float g_kv[(size_t)NRES * NSEQ * 16]; // [r][s][0..7]=k, [8..15]=v
__device__ float g_xn[(size_t)NSEQ * NRES * CM]; // tf32-rounded LN(act), [S,R,C]
__device__ float g_mskd[NRES * NSEQ];            // mask transposed [r][s]
__device__ float g_qsp[NRES * 8 * 64];           // partial masked sums per s-tile
__device__ float g_msp[NRES * 8];                // partial mask sums per s-tile
__device__ float g_gwf[4096];                    // fragment-packed tf32 gating_w
__device__ float g_owf[4096];                    // fragment-packed tf32 output_w

__device__ __forceinline__ void fma4(float4& a, float s, const float4 w) {
    a.x += s * w.x; a.y += s * w.y; a.z += s * w.z; a.w += s * w.w;
}
__device__ __forceinline__ uint32_t f2tf32(float f) {
    uint32_t r;
    asm("cvt.rna.tf32.f32 %0, %1;" : "=r"(r) : "f"(f));
    return r;
}
__device__ __forceinline__ void mma_tf32(float4& d,
    uint32_t a0, uint32_t a1, uint32_t a2, uint32_t a3,
    uint32_t b0, uint32_t b1) {
    asm volatile("mma.sync.aligned.m16n8k8.row.col.f32.tf32.tf32.f32 "
        "{%0,%1,%2,%3}, {%4,%5,%6,%7}, {%8,%9}, {%0,%1,%2,%3};"
        : "+f"(d.x), "+f"(d.y), "+f"(d.z), "+f"(d.w)
        : "r"(a0), "r"(a1), "r"(a2), "r"(a3), "r"(b0), "r"(b1));
}
__device__ __forceinline__ float sigf(float x) {
    return __fdividef(1.f, 1.f + __expf(-x));
}
__device__ __forceinline__ uint32_t su32(const void* p) {
    return (uint32_t)__cvta_generic_to_shared(p);
}
__device__ __forceinline__ void cpasync16(uint32_t dst, const void* src) {
    asm volatile("cp.async.cg.shared.global [%0], [%1], 16;" :: "r"(dst), "l"(src));
}
#define CP_COMMIT() asm volatile("cp.async.commit_group;")
#define CP_WAIT0()  asm volatile("cp.async.wait_group 0;")

// ---------------------------------------------------------------------------
// Kernel 0: one-shot weight fragment packing. grid = 16, 256 threads.
// ---------------------------------------------------------------------------
__global__ void msa_k0(const float* __restrict__ gating_w,
                       const float* __restrict__ output_w) {
    const int i = blockIdx.x * 256 + threadIdx.x;   // 0..4095
    const int c = i >> 6, j = i & 63;
    const int kk = c >> 3, tt = c & 7;
    const int nn = j >> 3, gg = j & 7;
    const int off = ((nn * 8 + kk) * 32 + gg * 4 + (tt & 3)) * 2 + (tt >> 2);
    g_gwf[off] = __uint_as_float(f2tf32(gating_w[i]));
    g_owf[off] = __uint_as_float(f2tf32(output_w[i]));
}

// ---------------------------------------------------------------------------
// Kernel 1a: LN + K/V projection + XN writeback. Block = 8 cols x 128 rows.
// grid = (96, 8), 256 threads, occupancy 2. Smem qsum pass (R10, correct).
// ---------------------------------------------------------------------------
#define RST 68

__global__ void __launch_bounds__(256, 2) msa_k1a(
    const float* __restrict__ act,      // [S, R, C]
    const float* __restrict__ mask,     // [S, R]
    const float* __restrict__ ln_scale, const float* __restrict__ ln_bias,
    const float* __restrict__ key_w,    // [64, 8]
    const float* __restrict__ value_w)  // [64, 8]
{
    extern __shared__ float smk[];
    float* xch = smk;            // 17408 : x -> xn(tf32) in place
    float* mch = xch + 17408;    // 256
    float* kws = mch + 256;      // 512
    float* vws = kws + 512;      // 512
    float* scl = vws + 512;      // 64
    float* bia = scl + 64;       // 64

    const int tid  = threadIdx.x;
    const int r0   = blockIdx.x * 8;
    const int ty   = blockIdx.y;
    const int s0   = ty * 128;
    const int w    = tid >> 5, lane = tid & 31;
    const int srl  = tid >> 3;      // compute row within chunk (0..31)
    const int cc   = tid & 7;       // compute column

    for (int i = tid; i < 512; i += 256) { kws[i] = key_w[i]; vws[i] = value_w[i]; }
    if (tid < 64) { scl[tid] = ln_scale[tid]; bia[tid] = ln_bias[tid]; }
    __syncthreads();

    const float4* kw4 = (const float4*)kws;
    const float4* vw4 = (const float4*)vws;
    const uint32_t xba = su32(xch);

    float q0 = 0.f, q1 = 0.f, msum = 0.f;   // warp w owns column w; lane owns ch 2l,2l+1

    for (int cs = 0; cs < 4; ++cs) {
        const int sb = s0 + cs * 32;

        // ---- stage via cp.async: 32 rows x 2KB contiguous ----
#pragma unroll
        for (int round = 0; round < 16; ++round) {
            const int j = round * 256 + tid;
            const int sr = j >> 7, f = j & 127;
            cpasync16(xba + ((sr * 8 + (f >> 4)) * RST + (f & 15) * 4) * 4,
                      act + ((size_t)(sb + sr) * NRES + r0) * CM + f * 4);
        }
        CP_COMMIT();
        mch[tid] = mask[(size_t)(sb + srl) * NRES + r0 + cc];
        CP_WAIT0();
        __syncthreads();

        // ---- compute: one thread per (s,c) row; LN + K/V; zero shuffles ----
        {
            float4* row4 = (float4*)(xch + (srl * 8 + cc) * RST);
            float sum = 0.f, ss = 0.f;
#pragma unroll
            for (int i = 0; i < 16; i++) {
                const float4 t = row4[i];
                sum += t.x + t.y + t.z + t.w;
                ss  += t.x*t.x + t.y*t.y + t.z*t.z + t.w*t.w;
            }
            const float mu = sum * (1.f / 64.f);
            const float var = ss * (1.f / 64.f) - mu * mu;
            const float rstd = rsqrtf(var + 1e-5f);

            float4 k0 = {0,0,0,0}, k1 = {0,0,0,0}, v0 = {0,0,0,0}, v1 = {0,0,0,0};
#pragma unroll
            for (int i = 0; i < 16; i++) {
                const float4 t = row4[i];
                float4 xn;
                xn.x = (t.x - mu) * rstd * scl[i*4+0] + bia[i*4+0];
                xn.y = (t.y - mu) * rstd * scl[i*4+1] + bia[i*4+1];
                xn.z = (t.z - mu) * rstd * scl[i*4+2] + bia[i*4+2];
                xn.w = (t.w - mu) * rstd * scl[i*4+3] + bia[i*4+3];
                fma4(k0, xn.x, kw4[(i*4+0)*2]); fma4(k1, xn.x, kw4[(i*4+0)*2+1]);
                fma4(v0, xn.x, vw4[(i*4+0)*2]); fma4(v1, xn.x, vw4[(i*4+0)*2+1]);
                fma4(k0, xn.y, kw4[(i*4+1)*2]); fma4(k1, xn.y, kw4[(i*4+1)*2+1]);
                fma4(v0, xn.y, vw4[(i*4+1)*2]); fma4(v1, xn.y, vw4[(i*4+1)*2+1]);
                fma4(k0, xn.z, kw4[(i*4+2)*2]); fma4(k1, xn.z, kw4[(i*4+2)*2+1]);
                fma4(v0, xn.z, vw4[(i*4+2)*2]); fma4(v1, xn.z, vw4[(i*4+2)*2+1]);
                fma4(k0, xn.w, kw4[(i*4+3)*2]); fma4(k1, xn.w, kw4[(i*4+3)*2+1]);
                fma4(v0, xn.w, vw4[(i*4+3)*2]); fma4(v1, xn.w, vw4[(i*4+3)*2+1]);
                xn.x = __uint_as_float(f2tf32(xn.x));
                xn.y = __uint_as_float(f2tf32(xn.y));
                xn.z = __uint_as_float(f2tf32(xn.z));
                xn.w = __uint_as_float(f2tf32(xn.w));
                row4[i] = xn;
            }
            float4* dst = (float4*)(g_kv + ((size_t)(r0 + cc) * NSEQ + sb + srl) * 16);
            dst[0] = k0; dst[1] = k1; dst[2] = v0; dst[3] = v1;
        }
        __syncthreads();

        // ---- XN writeback: coalesced 2KB rows ----
#pragma unroll
        for (int round = 0; round < 16; ++round) {
            const int j = round * 256 + tid;
            const int sr = j >> 7, f = j & 127;
            const float4 t = *(const float4*)(xch + (sr * 8 + (f >> 4)) * RST + (f & 15) * 4);
            ((float4*)(g_xn + ((size_t)(sb + sr) * NRES + r0) * CM))[f] = t;
        }

        // ---- qsum pass: warp w owns column w; lane owns channels 2l,2l+1 ----
        for (int sr = 0; sr < 32; ++sr) {
            const float mm = mch[sr * 8 + w];
            const float2 x2 = *(const float2*)(xch + (sr * 8 + w) * RST + 2 * lane);
            q0 += mm * x2.x;  q1 += mm * x2.y;
            msum += (lane == 0 ? mm : 0.f);
        }
        g_mskd[(r0 + w) * NSEQ + sb + lane] = mch[lane * 8 + w];
        __syncthreads();
    }

    *(float2*)(g_qsp + ((size_t)(r0 + w) * 8 + ty) * 64 + 2 * lane) = make_float2(q0, q1);
    if (lane == 0) g_msp[(r0 + w) * 8 + ty] = msum;
}

// ---------------------------------------------------------------------------
// Kernel 1b: softmax attention for one column. grid = 768, 256 threads.
// ---------------------------------------------------------------------------
__global__ void __launch_bounds__(256, 2) msa_k1b(
    const float* __restrict__ query_w)  // [64, 64]
{
    extern __shared__ float sm[];
    float* ks   = sm;              // 8192
    float* vs   = ks + 8192;       // 8192
    float* lsm  = vs + 8192;       // 8192
    float* msk  = lsm + 8192;      // 1024
    float* qsum = msk + 1024;      // 64
    float* qf   = qsum + 64;       // 64
    float* red  = qf + 64;         // 64
    float* gmax = red + 64;        // 8
    float* invZ = gmax + 8;        // 8
    float* part = invZ + 8;        // 256
    float* Msum = part + 256;      // 1   -> 26065 floats

    const int tid  = threadIdx.x;
    const int r    = blockIdx.x;
    const int lane = tid & 31;
    const int w    = tid >> 5;

    const float4* kv4 = (const float4*)(g_kv + (size_t)r * NSEQ * 16);
    float4* ks4 = (float4*)ks;
    float4* vs4 = (float4*)vs;
    for (int i = tid; i < 4096; i += 256) {
        const int s = i >> 2, q = i & 3;
        const float4 v = kv4[i];
        if (q < 2) ks4[s * 2 + q] = v;
        else       vs4[s * 2 + (q - 2)] = v;
    }
    for (int i = tid; i < 1024; i += 256) msk[i] = g_mskd[r * NSEQ + i];
    if (tid < 64) {
        float a = 0.f;
#pragma unroll
        for (int t = 0; t < 8; t++) a += g_qsp[((size_t)r * 8 + t) * 64 + tid];
        qsum[tid] = a;
    }
    if (tid == 64) {
        float a = 0.f;
#pragma unroll
        for (int t = 0; t < 8; t++) a += g_msp[r * 8 + t];
        *Msum = a;
    }
    __syncthreads();

    if (tid < 64) {
        const float invM = 1.f / (*Msum + 1e-10f);
        float acc = 0.f;
        for (int c = 0; c < 64; c++) acc += qsum[c] * query_w[c * 64 + tid];
        qf[tid] = acc * invM * 0.35355339059327373f;
    }
    __syncthreads();

    float lmax[8];
#pragma unroll
    for (int h = 0; h < 8; h++) lmax[h] = -3.4e38f;
#pragma unroll
    for (int it = 0; it < 4; it++) {
        const int s = tid + it * 256;
        const float4* kp = (const float4*)(ks + s * 8);
        const float4 k0 = kp[0], k1 = kp[1];
        const float b = 1e9f * (msk[s] - 1.f);
#pragma unroll
        for (int h = 0; h < 8; h++) {
            const float* q = qf + h * 8;
            float l = b + q[0]*k0.x + q[1]*k0.y + q[2]*k0.z + q[3]*k0.w
                        + q[4]*k1.x + q[5]*k1.y + q[6]*k1.z + q[7]*k1.w;
            lsm[s * 8 + h] = l;
            lmax[h] = fmaxf(lmax[h], l);
        }
    }
#pragma unroll
    for (int h = 0; h < 8; h++) {
#pragma unroll
        for (int off = 16; off; off >>= 1)
            lmax[h] = fmaxf(lmax[h], __shfl_xor_sync(0xffffffffu, lmax[h], off));
    }
    if (lane == 0) {
#pragma unroll
        for (int h = 0; h < 8; h++) red[w * 8 + h] = lmax[h];
    }
    __syncthreads();
    if (tid < 8) {
        float mm = red[tid];
#pragma unroll
        for (int ww = 1; ww < 8; ww++) mm = fmaxf(mm, red[ww * 8 + tid]);
        gmax[tid] = mm;
    }
    __syncthreads();

    float zl[8];
#pragma unroll
    for (int h = 0; h < 8; h++) zl[h] = 0.f;
#pragma unroll
    for (int it = 0; it < 4; it++) {
        const int s = tid + it * 256;
#pragma unroll
        for (int h = 0; h < 8; h++) {
            const float e = __expf(lsm[s * 8 + h] - gmax[h]);
            lsm[s * 8 + h] = e;
            zl[h] += e;
        }
    }
#pragma unroll
    for (int h = 0; h < 8; h++) {
#pragma unroll
        for (int off = 16; off; off >>= 1)
            zl[h] += __shfl_xor_sync(0xffffffffu, zl[h], off);
    }
    if (lane == 0) {
#pragma unroll
        for (int h = 0; h < 8; h++) red[w * 8 + h] = zl[h];
    }
    __syncthreads();
    if (tid < 8) {
        float z = 0.f;
#pragma unroll
        for (int ww = 0; ww < 8; ww++) z += red[ww * 8 + tid];
        invZ[tid] = 1.f / z;
    }
    __syncthreads();

    {
        const int hd = tid & 63, q4 = tid >> 6;
        const int h = hd >> 3, d = hd & 7;
        float p = 0.f;
        const int sb = q4 * 256;
        for (int s = sb; s < sb + 256; ++s)
            p += lsm[s * 8 + h] * vs[s * 8 + d];
        part[tid] = p;
    }
    __syncthreads();
    if (tid < 64) {
        const int h = tid >> 3;
        g_wa[r * 64 + tid] =
            (part[tid] + part[tid + 64] + part[tid + 128] + part[tid + 192]) * invZ[h];
    }
}

// ---------------------------------------------------------------------------
// Kernel 2: gate + output via tf32 MMA. Reads precomputed g_xn and
// fragment-packed weights via cp.async. grid = (768, 4), 256 threads.
// ---------------------------------------------------------------------------
#define XS 68

__global__ void __launch_bounds__(256, 2) msa_k2(
    const float* __restrict__ gating_b,  // [64]
    const float* __restrict__ output_b,  // [64]
    float* __restrict__ out)             // [S, R, C]
{
    extern __shared__ float sm2[];
    float* xnf = sm2;              // 256 rows * 68 = 17408
    float* gwf = xnf + 17408;      // 4096
    float* owf = gwf + 4096;       // 4096
    float* was = owf + 4096;       // 64
    float* gbs = was + 64;         // 64
    float* obs = gbs + 64;         // 64

    const int tid  = threadIdx.x;
    const int r    = blockIdx.x;
    const int s0   = blockIdx.y * 256;
    const int w    = tid >> 5, lane = tid & 31;
    const int c4   = lane & 15, rsel = lane >> 4;
    const int g    = lane >> 2, t = lane & 3;

    // ---- stage xn tile + weights via cp.async ----
    const uint32_t xba = su32(xnf);
    const uint32_t gba = su32(gwf);
    const uint32_t oba = su32(owf);
#pragma unroll
    for (int rnd = 0; rnd < 16; rnd++) {
        const int j = rnd * 256 + tid;        // float4 idx 0..4095
        const int row = j >> 4, f = j & 15;
        cpasync16(xba + (row * XS + f * 4) * 4,
                  g_xn + ((size_t)(s0 + row) * NRES + r) * CM + f * 4);
    }
#pragma unroll
    for (int rnd = 0; rnd < 4; rnd++) {
        const int j = rnd * 256 + tid;        // float4 idx 0..1023
        cpasync16(gba + j * 16, g_gwf + j * 4);
        cpasync16(oba + j * 16, g_owf + j * 4);
    }
    CP_COMMIT();

    if (tid < 64) {
        was[tid] = g_wa[r * 64 + tid];
        gbs[tid] = gating_b[tid];  obs[tid] = output_b[tid];
    }
    CP_WAIT0();
    __syncthreads();

    const int rb = w * 32;
    float* st0 = xnf + rb * XS;
    float* st1 = xnf + (rb + 16) * XS;

    // ---- GEMM1: logits = XN @ GW ----
    float4 acc0[8], acc1[8];
#pragma unroll
    for (int n = 0; n < 8; n++) { acc0[n] = make_float4(0,0,0,0); acc1[n] = make_float4(0,0,0,0); }
#pragma unroll
    for (int k = 0; k < 8; k++) {
        const int kc = k * 8 + t;
        const uint32_t a00 = __float_as_uint(st0[g * XS + kc]);
        const uint32_t a01 = __float_as_uint(st0[(g + 8) * XS + kc]);
        const uint32_t a02 = __float_as_uint(st0[g * XS + kc + 4]);
        const uint32_t a03 = __float_as_uint(st0[(g + 8) * XS + kc + 4]);
        const uint32_t a10 = __float_as_uint(st1[g * XS + kc]);
        const uint32_t a11 = __float_as_uint(st1[(g + 8) * XS + kc]);
        const uint32_t a12 = __float_as_uint(st1[g * XS + kc + 4]);
        const uint32_t a13 = __float_as_uint(st1[(g + 8) * XS + kc + 4]);
#pragma unroll
        for (int n = 0; n < 8; n++) {
            const float2 b = *(const float2*)(gwf + ((n * 8 + k) * 32 + lane) * 2);
            mma_tf32(acc0[n], a00, a01, a02, a03,
                     __float_as_uint(b.x), __float_as_uint(b.y));
            mma_tf32(acc1[n], a10, a11, a12, a13,
                     __float_as_uint(b.x), __float_as_uint(b.y));
        }
    }
    __syncwarp();

    // ---- gate: G = wa*sigmoid(logit+gb) ----
#pragma unroll
    for (int n = 0; n < 8; n++) {
        const int c0 = n * 8 + 2 * t;
        const float w0 = was[c0], w1 = was[c0 + 1];
        const float b0 = gbs[c0], b1 = gbs[c0 + 1];
        float2 p;
        p.x = __uint_as_float(f2tf32(w0 * sigf(acc0[n].x + b0)));
        p.y = __uint_as_float(f2tf32(w1 * sigf(acc0[n].y + b1)));
        *(float2*)(st0 + g * XS + c0) = p;
        p.x = __uint_as_float(f2tf32(w0 * sigf(acc0[n].z + b0)));
        p.y = __uint_as_float(f2tf32(w1 * sigf(acc0[n].w + b1)));
        *(float2*)(st0 + (g + 8) * XS + c0) = p;
        p.x = __uint_as_float(f2tf32(w0 * sigf(acc1[n].x + b0)));
        p.y = __uint_as_float(f2tf32(w1 * sigf(acc1[n].y + b1)));
        *(float2*)(st1 + g * XS + c0) = p;
        p.x = __uint_as_float(f2tf32(w0 * sigf(acc1[n].z + b0)));
        p.y = __uint_as_float(f2tf32(w1 * sigf(acc1[n].w + b1)));
        *(float2*)(st1 + (g + 8) * XS + c0) = p;
    }
    __syncwarp();

    // ---- GEMM2: OUT = G @ OW + ob ----
    float4 o0[8], o1[8];
#pragma unroll
    for (int n = 0; n < 8; n++) {
        const int c0 = n * 8 + 2 * t;
        o0[n] = make_float4(obs[c0], obs[c0+1], obs[c0], obs[c0+1]);
        o1[n] = o0[n];
    }
#pragma unroll
    for (int k = 0; k < 8; k++) {
        const int kc = k * 8 + t;
        const uint32_t a00 = __float_as_uint(st0[g * XS + kc]);
        const uint32_t a01 = __float_as_uint(st0[(g + 8) * XS + kc]);
        const uint32_t a02 = __float_as_uint(st0[g * XS + kc + 4]);
        const uint32_t a03 = __float_as_uint(st0[(g + 8) * XS + kc + 4]);
        const uint32_t a10 = __float_as_uint(st1[g * XS + kc]);
        const uint32_t a11 = __float_as_uint(st1[(g + 8) * XS + kc]);
        const uint32_t a12 = __float_as_uint(st1[g * XS + kc + 4]);
        const uint32_t a13 = __float_as_uint(st1[(g + 8) * XS + kc + 4]);
#pragma unroll
        for (int n = 0; n < 8; n++) {
            const float2 b = *(const float2*)(owf + ((n * 8 + k) * 32 + lane) * 2);
            mma_tf32(o0[n], a00, a01, a02, a03,
                     __float_as_uint(b.x), __float_as_uint(b.y));
            mma_tf32(o1[n], a10, a11, a12, a13,
                     __float_as_uint(b.x), __float_as_uint(b.y));
        }
    }
    __syncwarp();

    // ---- stage outputs row-major ----
#pragma unroll
    for (int n = 0; n < 8; n++) {
        const int c0 = n * 8 + 2 * t;
        *(float2*)(st0 + g * XS + c0)       = make_float2(o0[n].x, o0[n].y);
        *(float2*)(st0 + (g + 8) * XS + c0) = make_float2(o0[n].z, o0[n].w);
        *(float2*)(st1 + g * XS + c0)       = make_float2(o1[n].x, o1[n].y);
        *(float2*)(st1 + (g + 8) * XS + c0) = make_float2(o1[n].z, o1[n].w);
    }
    __syncwarp();

    // ---- coalesced STG ----
#pragma unroll
    for (int rnd = 0; rnd < 16; rnd++) {
        const int row = w * 32 + rnd * 2 + rsel;
        const float4 v = *(const float4*)(xnf + row * XS + c4 * 4);
        *(float4*)(out + ((size_t)(s0 + row) * NRES + r) * CM + c4 * 4) = v;
    }
}

// ---------------------------------------------------------------------------
#define K1A_SMEM (18816 * 4)
#define K1B_SMEM (26065 * 4)
#define K2_SMEM  (25792 * 4)

extern "C" void kernel_launch(void* const* d_in, const int* in_sizes, int n_in,
                              void* d_out, int out_size) {
    (void)in_sizes; (void)n_in; (void)out_size;
    const float* act      = (const float*)d_in[0];
    const float* mask     = (const float*)d_in[1];
    const float* ln_scale = (const float*)d_in[2];
    const float* ln_bias  = (const float*)d_in[3];
    const float* query_w  = (const float*)d_in[4];
    const float* key_w    = (const float*)d_in[5];
    const float* value_w  = (const float*)d_in[6];
    const float* gating_w = (const float*)d_in[7];
    const float* gating_b = (const float*)d_in[8];
    const float* output_w = (const float*)d_in[9];
    const float* output_b = (const float*)d_in[10];
    float* out = (float*)d_out;

    cudaFuncSetAttribute(msa_k1a, cudaFuncAttributeMaxDynamicSharedMemorySize, K1A_SMEM);
    cudaFuncSetAttribute(msa_k1b, cudaFuncAttributeMaxDynamicSharedMemorySize, K1B_SMEM);
    cudaFuncSetAttribute(msa_k2,  cudaFuncAttributeMaxDynamicSharedMemorySize, K2_SMEM);

    msa_k0<<<16, 256>>>(gating_w, output_w);
    msa_k1a<<<dim3(96, 8), 256, K1A_SMEM>>>(act, mask, ln_scale, ln_bias, key_w, value_w);
    msa_k1b<<<NRES, 256, K1B_SMEM>>>(query_w);
    msa_k2<<<dim3(NRES, 4), 256, K2_SMEM>>>(gating_b, output_b, out);
}